// round 8
// baseline (speedup 1.0000x reference)
#include <cuda_runtime.h>
#include <cuda_bf16.h>
#include <stdint.h>

#define NTH 256
#define BSTRIDE 147456               // floats per batch (384*384)
static const float INV_SQRT_D = 0.05103103630798288f;

#define NPAIR 18874368               // 256*384*192
#define TILE_U32 2048                // uint32 per 128x32 fragment tile (8KB)
#define WTILES (36 * TILE_U32)

// fragment-ordered 128x32 operand tiles
__device__ uint32_t g_zh[NPAIR],  g_zl[NPAIR];    // z, offA (A-operand)
__device__ uint32_t g_zbh[NPAIR], g_zbl[NPAIR];   // z, offB (B-operand, attn)
__device__ uint32_t g_Yh[NPAIR],  g_Yl[NPAIR];    // Y = z*(Wq^T Wk), offA
__device__ uint32_t g_Vth[NPAIR], g_Vtl[NPAIR];   // V transposed, offB
__device__ uint32_t g_Ph[NPAIR],  g_Pl[NPAIR];    // exp(scores), offA
__device__ uint32_t g_wqTh[WTILES], g_wqTl[WTILES];  // Wq^T, offA
__device__ uint32_t g_wkTh[WTILES], g_wkTl[WTILES];  // Wk^T, offB
__device__ uint32_t g_wvh[WTILES],  g_wvl[WTILES];   // Wv rows, offB
__device__ uint32_t g_Abh[WTILES],  g_Abl[WTILES];   // A=Wq^T Wk, offB
__device__ float    g_a2[384];                       // Wk^T bq
__device__ float    g_v[98304];                      // z . a2
__device__ float    g_rsp[3 * 98304];                // per-kt row partial sums

#define NSTAGE 3
#define STAGE_BYTES 32768            // A_HI 8K | A_LO 8K | B_HI 8K | B_LO 8K
#define SMEM_BYTES (NSTAGE * STAGE_BYTES)   // 96KB -> 2 CTAs/SM

__device__ __forceinline__ int offA(int r, int p) {
    return ((p >> 3) << 12) + ((r >> 4) << 9) +
           (((r & 7) * 4 + (p & 3)) << 4) +
           (((p >> 2) & 1) << 3) + (((r >> 3) & 1) << 2);
}
__device__ __forceinline__ int offB(int n, int p) {
    return ((p >> 3) << 12) + ((n >> 3) << 8) +
           (((n & 7) * 4 + (p & 3)) << 3) + (((p >> 2) & 1) << 2);
}

#define MMA(d, a, b) \
    asm volatile("mma.sync.aligned.m16n8k16.row.col.f32.bf16.bf16.f32 " \
        "{%0,%1,%2,%3},{%4,%5,%6,%7},{%8,%9},{%0,%1,%2,%3};" \
        : "+f"((d)[0]), "+f"((d)[1]), "+f"((d)[2]), "+f"((d)[3]) \
        : "r"((a).x), "r"((a).y), "r"((a).z), "r"((a).w), \
          "r"((b).x), "r"((b).y))

#define CP16(sa, gp) \
    asm volatile("cp.async.cg.shared.global [%0], [%1], 16;" :: "r"(sa), "l"(gp))
#define CP_COMMIT() asm volatile("cp.async.commit_group;" ::: "memory")
#define CP_WAIT1()  asm volatile("cp.async.wait_group 1;" ::: "memory")
#define CP_WAIT0()  asm volatile("cp.async.wait_group 0;" ::: "memory")

__device__ __forceinline__ uint32_t smem_u32(const void* p) {
    uint32_t a;
    asm("{ .reg .u64 t; cvta.to.shared.u64 t, %1; cvt.u32.u64 %0, t; }"
        : "=r"(a) : "l"(p));
    return a;
}

__device__ __forceinline__ void splitpack(float x, float y,
                                          uint32_t& hi, uint32_t& lo) {
    __nv_bfloat16 hx = __float2bfloat16(x);
    __nv_bfloat16 hy = __float2bfloat16(y);
    float lx = x - __bfloat162float(hx);
    float ly = y - __bfloat162float(hy);
    __nv_bfloat162 h2 = __halves2bfloat162(hx, hy);
    __nv_bfloat162 l2 = __floats2bfloat162_rn(lx, ly);
    hi = reinterpret_cast<uint32_t&>(h2);
    lo = reinterpret_cast<uint32_t&>(l2);
}

// fast e^x on the FMA pipe (poly exp2, rel err ~2e-6); input range |x| < 25
__device__ __forceinline__ float fast_exp(float x) {
    float y = x * 1.4426950408889634f;
    int ir = __float2int_rn(y);
    float f = (y - (float)ir) * 0.6931471805599453f;
    float p = 1.0f + f * (1.0f + f * (0.5f + f * (0.16666667f +
              f * (0.041666667f + f * 0.0083333333f))));
    return p * __int_as_float((ir + 127) << 23);
}

// ---------------- a2 = Wk^T bq ----------------
__global__ void a2_kernel(const float* __restrict__ Wk,
                          const float* __restrict__ bq) {
    int d = threadIdx.x;
    float s = 0.0f;
    for (int f = 0; f < 384; f++) s += Wk[(size_t)f * 384 + d] * bq[f];
    g_a2[d] = s;
}

// -------- presplit z: offA + offB tiles, fused v = z.a2 --------
__global__ __launch_bounds__(256) void presplit_z(const float* __restrict__ z) {
    const int row = blockIdx.x * 8 + (threadIdx.x >> 5);
    const int lane = threadIdx.x & 31;
    const float* p = z + (size_t)row * 384 + lane * 12;

    float v[12];
    *(float4*)&v[0] = *(const float4*)(p);
    *(float4*)&v[4] = *(const float4*)(p + 4);
    *(float4*)&v[8] = *(const float4*)(p + 8);

    float a[12];
    *(float4*)&a[0] = *(const float4*)(g_a2 + lane * 12);
    *(float4*)&a[4] = *(const float4*)(g_a2 + lane * 12 + 4);
    *(float4*)&a[8] = *(const float4*)(g_a2 + lane * 12 + 8);

    float dot = 0.0f;
#pragma unroll
    for (int j = 0; j < 12; j++) dot += v[j] * a[j];
#pragma unroll
    for (int o = 16; o > 0; o >>= 1)
        dot += __shfl_xor_sync(0xffffffffu, dot, o);
    if (lane == 0) g_v[row] = dot;

    const int rl = row & 127;
    const size_t tb0 = (size_t)(row >> 7) * 12;
#pragma unroll
    for (int p6 = 0; p6 < 6; p6++) {
        int kp = lane * 6 + p6;
        uint32_t h, l;
        splitpack(v[2 * p6], v[2 * p6 + 1], h, l);
        size_t tile = (tb0 + (kp >> 4)) * TILE_U32;
        size_t oa = tile + (offA(rl, kp & 15) >> 2);
        size_t ob = tile + (offB(rl, kp & 15) >> 2);
        g_zh[oa] = h;  g_zl[oa] = l;
        g_zbh[ob] = h; g_zbl[ob] = l;
    }
}

// -------- presplit weights: WqT(offA), WkT(offB), Wv(offB) --------
__global__ __launch_bounds__(256) void presplit_weights(
    const float* __restrict__ Wq, const float* __restrict__ Wk,
    const float* __restrict__ Wv)
{
    const int which = blockIdx.y;
    const int idx = blockIdx.x * 256 + threadIdx.x;   // < 73728
    if (which == 0) {
        int d = idx / 192, fp = idx % 192;
        float x = Wq[(size_t)(2 * fp) * 384 + d];
        float y = Wq[(size_t)(2 * fp + 1) * 384 + d];
        uint32_t h, l; splitpack(x, y, h, l);
        size_t o = (size_t)((d >> 7) * 12 + (fp >> 4)) * TILE_U32 +
                   (offA(d & 127, fp & 15) >> 2);
        g_wqTh[o] = h; g_wqTl[o] = l;
    } else if (which == 1) {
        int e = idx / 192, fp = idx % 192;
        float x = Wk[(size_t)(2 * fp) * 384 + e];
        float y = Wk[(size_t)(2 * fp + 1) * 384 + e];
        uint32_t h, l; splitpack(x, y, h, l);
        size_t o = (size_t)((e >> 7) * 12 + (fp >> 4)) * TILE_U32 +
                   (offB(e & 127, fp & 15) >> 2);
        g_wkTh[o] = h; g_wkTl[o] = l;
    } else {
        int ng = idx / 192, kp = idx % 192;
        float2 vv = *(const float2*)&Wv[(size_t)ng * 384 + kp * 2];
        uint32_t h, l; splitpack(vv.x, vv.y, h, l);
        size_t o = (size_t)((ng >> 7) * 12 + (kp >> 4)) * TILE_U32 +
                   (offB(ng & 127, kp & 15) >> 2);
        g_wvh[o] = h; g_wvl[o] = l;
    }
}

// ---------------------------------------------------------------------------
// MODE 0: Y & V projections grid(6,768)
// MODE 1: fused scores+exp: P=exp((Y z^T + v)/sqrt d), rowsums. grid(6,256)
// MODE 2: out = (P V) / rowsum. grid(3,3,256)
// MODE 3: A = Wq^T Wk. grid(3,3)
// ---------------------------------------------------------------------------
template <int MODE>
__global__ __launch_bounds__(NTH, 2) void gemm(
    const float* __restrict__ bias, float* __restrict__ outp)
{
    extern __shared__ __align__(16) char sm[];
    const uint32_t smb = smem_u32(sm);
    const int tid = threadIdx.x;
    const int lane = tid & 31;
    const int wid = tid >> 5;
    const int wm = wid >> 2;
    const int wn = wid & 3;

    const uint32_t *Ah, *Al, *Bh, *Bl;
    int NKT, n0 = 0, m0 = 0, w = 0, mt = 0, b = 0;

    if (MODE == 0) {
        w = blockIdx.x / 3;                 // 0 = Y, 1 = V
        int nt = blockIdx.x % 3;
        n0 = nt * 128;
        Ah = g_zh + (size_t)blockIdx.y * 24576;
        Al = g_zl + (size_t)blockIdx.y * 24576;
        if (w == 0) { Bh = g_Abh + nt * 12 * TILE_U32; Bl = g_Abl + nt * 12 * TILE_U32; }
        else        { Bh = g_wvh + nt * 12 * TILE_U32; Bl = g_wvl + nt * 12 * TILE_U32; }
        NKT = 12;
    } else if (MODE == 1) {
        // q-tile rows x k-tile cols, lower triangle: mt=q tile, nt=k tile
        const int mtab[6] = {0, 1, 1, 2, 2, 2};
        const int ntab[6] = {0, 0, 1, 0, 1, 2};
        mt = mtab[blockIdx.x];
        int nt = ntab[blockIdx.x];
        b = blockIdx.y;
        m0 = mt * 128; n0 = nt * 128;
        Ah = g_Yh + (size_t)(b * 3 + mt) * 24576;
        Al = g_Yl + (size_t)(b * 3 + mt) * 24576;
        Bh = g_zbh + (size_t)(b * 3 + nt) * 24576;
        Bl = g_zbl + (size_t)(b * 3 + nt) * 24576;
        NKT = 12;
    } else if (MODE == 2) {
        int nt = blockIdx.x; mt = blockIdx.y; b = blockIdx.z;
        m0 = mt * 128; n0 = nt * 128;
        Ah = g_Ph + (size_t)(b * 3 + mt) * 24576;
        Al = g_Pl + (size_t)(b * 3 + mt) * 24576;
        Bh = g_Vth + (size_t)(b * 3 + nt) * 24576;
        Bl = g_Vtl + (size_t)(b * 3 + nt) * 24576;
        NKT = (mt + 1) * 4;
    } else {
        int nt = blockIdx.x; mt = blockIdx.y;
        m0 = mt * 128; n0 = nt * 128;
        Ah = g_wqTh + (size_t)mt * 24576;
        Al = g_wqTl + (size_t)mt * 24576;
        Bh = g_wkTh + (size_t)nt * 24576;
        Bl = g_wkTl + (size_t)nt * 24576;
        NKT = 12;
    }

    auto issue = [&](int kt, int st) {
        const uint32_t d0 = smb + st * STAGE_BYTES + tid * 16;
        const int go = kt * TILE_U32 + tid * 4;
        CP16(d0,              Ah + go);  CP16(d0 + 4096,          Ah + go + 1024);
        CP16(d0 + 8192,       Al + go);  CP16(d0 + 8192 + 4096,   Al + go + 1024);
        CP16(d0 + 16384,      Bh + go);  CP16(d0 + 16384 + 4096,  Bh + go + 1024);
        CP16(d0 + 24576,      Bl + go);  CP16(d0 + 24576 + 4096,  Bl + go + 1024);
    };

    issue(0, 0); CP_COMMIT();
    issue(1, 1); CP_COMMIT();

    float acc[4][4][4];
#pragma unroll
    for (int i = 0; i < 4; i++)
#pragma unroll
        for (int j = 0; j < 4; j++)
#pragma unroll
            for (int r = 0; r < 4; r++) acc[i][j][r] = 0.0f;

    int cs = 0, is = 2;
    for (int kt = 0; kt < NKT; kt++) {
        CP_WAIT1();
        __syncthreads();
        if (kt + 2 < NKT) issue(kt + 2, is);
        CP_COMMIT();

        const char* base = sm + cs * STAGE_BYTES;
#pragma unroll
        for (int s = 0; s < 2; s++) {
            uint4 ah[4], al[4];
#pragma unroll
            for (int i = 0; i < 4; i++) {
                int off = s * 4096 + (wm * 4 + i) * 512 + lane * 16;
                ah[i] = *(const uint4*)(base + off);
                al[i] = *(const uint4*)(base + 8192 + off);
            }
#pragma unroll
            for (int j = 0; j < 4; j++) {
                int off = s * 4096 + (wn * 4 + j) * 256 + lane * 8;
                uint2 bh = *(const uint2*)(base + 16384 + off);
                uint2 bl = *(const uint2*)(base + 24576 + off);
#pragma unroll
                for (int i = 0; i < 4; i++) MMA(acc[i][j], ah[i], bh);
#pragma unroll
                for (int i = 0; i < 4; i++) MMA(acc[i][j], ah[i], bl);
#pragma unroll
                for (int i = 0; i < 4; i++) MMA(acc[i][j], al[i], bh);
            }
        }
        cs = (cs == 2) ? 0 : cs + 1;
        is = (is == 2) ? 0 : is + 1;
    }

    // ---- epilogues ----
    const int g = lane >> 2, t = lane & 3;

    if (MODE == 0 && w == 0) {
        // Y: offA fragment tiles keyed by row-tile
        const size_t tb0 = (size_t)blockIdx.y * 12;
#pragma unroll
        for (int i = 0; i < 4; i++) {
            const int rl = wm * 64 + i * 16 + g;
#pragma unroll
            for (int j = 0; j < 4; j++) {
                const int c0 = n0 + wn * 32 + j * 8 + t * 2;
                uint32_t h0, l0, h1, l1;
                splitpack(acc[i][j][0], acc[i][j][1], h0, l0);
                splitpack(acc[i][j][2], acc[i][j][3], h1, l1);
                size_t tile = (tb0 + (c0 >> 5)) * TILE_U32;
                int p = (c0 & 31) >> 1;
                size_t o1 = tile + (offA(rl, p) >> 2);
                size_t o2 = tile + (offA(rl + 8, p) >> 2);
                g_Yh[o1] = h0; g_Yl[o1] = l0;
                g_Yh[o2] = h1; g_Yl[o2] = l1;
            }
        }
    } else if (MODE == 0) {
        // V: stage fp32 tile, transposed fragment write to Vt (offB)
        CP_WAIT0();
        __syncthreads();
        float* s = (float*)sm;   // [128][132]
#pragma unroll
        for (int i = 0; i < 4; i++) {
            const int rl = wm * 64 + i * 16 + g;
#pragma unroll
            for (int j = 0; j < 4; j++) {
                const int c = wn * 32 + j * 8 + t * 2;
                float b0 = bias[n0 + c], b1 = bias[n0 + c + 1];
                s[rl * 132 + c]           = acc[i][j][0] + b0;
                s[rl * 132 + c + 1]       = acc[i][j][1] + b1;
                s[(rl + 8) * 132 + c]     = acc[i][j][2] + b0;
                s[(rl + 8) * 132 + c + 1] = acc[i][j][3] + b1;
            }
        }
        __syncthreads();
        const int bb = blockIdx.y / 3;
        const int l0tok = (blockIdx.y % 3) * 128;
#pragma unroll
        for (int it = 0; it < 8; it++) {
            int idx = it * 256 + tid;
            int dl = idx & 127;
            int tb = (idx >> 7) * 8;
            float v[8];
#pragma unroll
            for (int u = 0; u < 8; u++) v[u] = s[(tb + u) * 132 + dl];
            int tok0 = l0tok + tb;
            size_t tile = (size_t)((bb * 3 + (n0 >> 7)) * 12 + (tok0 >> 5)) * TILE_U32;
            int p0 = (tok0 & 31) >> 1;
#pragma unroll
            for (int pp = 0; pp < 4; pp++) {
                uint32_t h, l;
                splitpack(v[2 * pp], v[2 * pp + 1], h, l);
                size_t o = tile + (offB(dl, p0 + pp) >> 2);
                g_Vth[o] = h; g_Vtl[o] = l;
            }
        }
    } else if (MODE == 1) {
        // fused: mask + exp (unnormalized) + rowsums + coalesced P tiles
        CP_WAIT0();
        __syncthreads();
        uint32_t* sp = (uint32_t*)sm;           // staging: hi 32KB, lo 32KB
        float* rs4 = (float*)(sm + 65536);      // [4][128]
        const float* vv = g_v + (size_t)b * 384;

        float rsum[4][2];
#pragma unroll
        for (int i = 0; i < 4; i++) { rsum[i][0] = 0.0f; rsum[i][1] = 0.0f; }

#pragma unroll
        for (int i = 0; i < 4; i++) {
            const int rl = wm * 64 + i * 16 + g;
            const int q0 = m0 + rl, q1 = q0 + 8;
#pragma unroll
            for (int j = 0; j < 4; j++) {
                const int c0 = n0 + wn * 32 + j * 8 + t * 2;
                float vk0 = vv[c0], vk1 = vv[c0 + 1];
                float p0 = (c0     <= q0) ? fast_exp((acc[i][j][0] + vk0) * INV_SQRT_D) : 0.0f;
                float p1 = (c0 + 1 <= q0) ? fast_exp((acc[i][j][1] + vk1) * INV_SQRT_D) : 0.0f;
                float p2 = (c0     <= q1) ? fast_exp((acc[i][j][2] + vk0) * INV_SQRT_D) : 0.0f;
                float p3 = (c0 + 1 <= q1) ? fast_exp((acc[i][j][3] + vk1) * INV_SQRT_D) : 0.0f;
                rsum[i][0] += p0 + p1;
                rsum[i][1] += p2 + p3;
                uint32_t h0, l0, h1, l1;
                splitpack(p0, p1, h0, l0);
                splitpack(p2, p3, h1, l1);
                int kp = (c0 - n0) >> 1;
                int sub = kp >> 4, kpp = kp & 15;
                int o1 = (sub * 8192 + offA(rl, kpp)) >> 2;
                int o2 = (sub * 8192 + offA(rl + 8, kpp)) >> 2;
                sp[o1] = h0; sp[o1 + 8192] = l0;
                sp[o2] = h1; sp[o2 + 8192] = l1;
            }
        }
        // reduce rowsums across quad lanes (t)
#pragma unroll
        for (int i = 0; i < 4; i++) {
#pragma unroll
            for (int h = 0; h < 2; h++) {
                rsum[i][h] += __shfl_xor_sync(0xffffffffu, rsum[i][h], 1);
                rsum[i][h] += __shfl_xor_sync(0xffffffffu, rsum[i][h], 2);
            }
        }
        if (t == 0) {
#pragma unroll
            for (int i = 0; i < 4; i++) {
                int rl = wm * 64 + i * 16 + g;
                rs4[wn * 128 + rl]     = rsum[i][0];
                rs4[wn * 128 + rl + 8] = rsum[i][1];
            }
        }
        __syncthreads();
        // coalesced P tile writes (4 subtiles x 8KB, hi + lo)
        size_t gbase = ((size_t)(b * 3 + mt) * 12 + (n0 >> 5)) * TILE_U32;
#pragma unroll
        for (int s4 = 0; s4 < 4; s4++) {
            size_t tb = gbase + s4 * TILE_U32;
#pragma unroll
            for (int it = 0; it < 2; it++) {
                int o = it * 1024 + tid * 4;
                *(uint4*)&g_Ph[tb + o] = *(const uint4*)&sp[s4 * 2048 + o];
                *(uint4*)&g_Pl[tb + o] = *(const uint4*)&sp[8192 + s4 * 2048 + o];
            }
        }
        if (tid < 128) {
            float ssum = rs4[tid] + rs4[128 + tid] + rs4[256 + tid] + rs4[384 + tid];
            g_rsp[(size_t)(n0 >> 7) * 98304 + (size_t)b * 384 + m0 + tid] = ssum;
        }
    } else if (MODE == 2) {
        float* Oo = outp + (size_t)b * BSTRIDE;
#pragma unroll
        for (int i = 0; i < 4; i++) {
            const int r0 = m0 + wm * 64 + i * 16 + g;
            float s0 = 0.0f, s1 = 0.0f;
            for (int k = 0; k <= mt; k++) {
                s0 += g_rsp[(size_t)k * 98304 + (size_t)b * 384 + r0];
                s1 += g_rsp[(size_t)k * 98304 + (size_t)b * 384 + r0 + 8];
            }
            float inv0 = 1.0f / s0, inv1 = 1.0f / s1;
#pragma unroll
            for (int j = 0; j < 4; j++) {
                const int c0 = n0 + wn * 32 + j * 8 + t * 2;
                *(float2*)&Oo[(size_t)r0 * 384 + c0] =
                    make_float2(acc[i][j][0] * inv0, acc[i][j][1] * inv0);
                *(float2*)&Oo[(size_t)(r0 + 8) * 384 + c0] =
                    make_float2(acc[i][j][2] * inv1, acc[i][j][3] * inv1);
            }
        }
    } else {
        // MODE 3: A[d,e] -> transpose-write g_Ab as offB (n=e, k=d)
        CP_WAIT0();
        __syncthreads();
        float* s = (float*)sm;   // [128 d][132 e]
#pragma unroll
        for (int i = 0; i < 4; i++) {
            const int rl = wm * 64 + i * 16 + g;
#pragma unroll
            for (int j = 0; j < 4; j++) {
                const int c = wn * 32 + j * 8 + t * 2;
                s[rl * 132 + c]           = acc[i][j][0];
                s[rl * 132 + c + 1]       = acc[i][j][1];
                s[(rl + 8) * 132 + c]     = acc[i][j][2];
                s[(rl + 8) * 132 + c + 1] = acc[i][j][3];
            }
        }
        __syncthreads();
#pragma unroll
        for (int it = 0; it < 8; it++) {
            int idx = it * 256 + tid;
            int el = idx & 127;
            int db = (idx >> 7) * 8;
            float v[8];
#pragma unroll
            for (int u = 0; u < 8; u++) v[u] = s[(db + u) * 132 + el];
            int k0 = m0 + db;
            size_t tile = (size_t)((n0 >> 7) * 12 + (k0 >> 5)) * TILE_U32;
            int p0 = (k0 & 31) >> 1;
#pragma unroll
            for (int pp = 0; pp < 4; pp++) {
                uint32_t h, l;
                splitpack(v[2 * pp], v[2 * pp + 1], h, l);
                size_t o = tile + (offB(el, p0 + pp) >> 2);
                g_Abh[o] = h; g_Abl[o] = l;
            }
        }
    }
}

// ---------------------------------------------------------------------------
extern "C" void kernel_launch(void* const* d_in, const int* in_sizes, int n_in,
                              void* d_out, int out_size)
{
    const float* z  = (const float*)d_in[0];
    const float* Wq = (const float*)d_in[1];
    const float* bq = (const float*)d_in[2];
    const float* Wk = (const float*)d_in[3];
    const float* Wv = (const float*)d_in[5];
    const float* bv = (const float*)d_in[6];
    float* out = (float*)d_out;

    cudaFuncSetAttribute(gemm<0>, cudaFuncAttributeMaxDynamicSharedMemorySize, SMEM_BYTES);
    cudaFuncSetAttribute(gemm<1>, cudaFuncAttributeMaxDynamicSharedMemorySize, SMEM_BYTES);
    cudaFuncSetAttribute(gemm<2>, cudaFuncAttributeMaxDynamicSharedMemorySize, SMEM_BYTES);
    cudaFuncSetAttribute(gemm<3>, cudaFuncAttributeMaxDynamicSharedMemorySize, SMEM_BYTES);

    dim3 blk(NTH);

    a2_kernel<<<1, 384>>>(Wk, bq);
    presplit_z<<<12288, blk>>>(z);
    presplit_weights<<<dim3(288, 3), blk>>>(Wq, Wk, Wv);

    // A = Wq^T Wk (tiny)
    gemm<3><<<dim3(3, 3), blk, SMEM_BYTES>>>(nullptr, nullptr);

    // Y = z A (offA) and V = z Wv^T + bv (offB, transposed)
    gemm<0><<<dim3(6, 768), blk, SMEM_BYTES>>>(bv, nullptr);

    // fused scores + exp -> P tiles + rowsum partials (lower triangle only)
    gemm<1><<<dim3(6, 256), blk, SMEM_BYTES>>>(nullptr, nullptr);

    // out = (P V) / rowsum
    gemm<2><<<dim3(3, 3, 256), blk, SMEM_BYTES>>>(nullptr, out);
}

// round 9
// speedup vs baseline: 1.3860x; 1.3860x over previous
#include <cuda_runtime.h>
#include <cuda_bf16.h>
#include <stdint.h>

#define NTH 256
#define BSTRIDE 147456               // floats per batch (384*384)
static const float INV_SQRT_D = 0.05103103630798288f;

#define NPAIR 18874368               // 256*384*192
#define TILE_U32 2048                // uint32 per 128x32 fragment tile (8KB)
#define WTILES (36 * TILE_U32)

// fragment-ordered 128x32 operand tiles
__device__ uint32_t g_zh[NPAIR],  g_zl[NPAIR];    // z, offA (A-operand)
__device__ uint32_t g_zbh[NPAIR], g_zbl[NPAIR];   // z, offB (B-operand, attn)
__device__ uint32_t g_Yh[NPAIR],  g_Yl[NPAIR];    // Y = z*(Wq^T Wk), offA
__device__ uint32_t g_Vth[NPAIR], g_Vtl[NPAIR];   // V transposed, offB
__device__ uint32_t g_Ph[NPAIR],  g_Pl[NPAIR];    // exp(scores), offA
__device__ uint32_t g_wqTh[WTILES], g_wqTl[WTILES];  // Wq^T, offA
__device__ uint32_t g_wkTh[WTILES], g_wkTl[WTILES];  // Wk^T, offB
__device__ uint32_t g_wvh[WTILES],  g_wvl[WTILES];   // Wv rows, offB
__device__ uint32_t g_Abh[WTILES],  g_Abl[WTILES];   // A=Wq^T Wk, offB
__device__ float    g_a2[384];                       // Wk^T bq
__device__ float    g_v[98304];                      // z . a2
__device__ float    g_rsp[3 * 98304];                // per-kt row partial sums

#define NSTAGE 3
#define STAGE_BYTES 32768            // A_HI 8K | A_LO 8K | B_HI 8K | B_LO 8K
#define SMEM_BYTES (NSTAGE * STAGE_BYTES)   // 96KB -> 2 CTAs/SM

__device__ __forceinline__ int offA(int r, int p) {
    return ((p >> 3) << 12) + ((r >> 4) << 9) +
           (((r & 7) * 4 + (p & 3)) << 4) +
           (((p >> 2) & 1) << 3) + (((r >> 3) & 1) << 2);
}
__device__ __forceinline__ int offB(int n, int p) {
    return ((p >> 3) << 12) + ((n >> 3) << 8) +
           (((n & 7) * 4 + (p & 3)) << 3) + (((p >> 2) & 1) << 2);
}

#define MMA(d, a, b) \
    asm volatile("mma.sync.aligned.m16n8k16.row.col.f32.bf16.bf16.f32 " \
        "{%0,%1,%2,%3},{%4,%5,%6,%7},{%8,%9},{%0,%1,%2,%3};" \
        : "+f"((d)[0]), "+f"((d)[1]), "+f"((d)[2]), "+f"((d)[3]) \
        : "r"((a).x), "r"((a).y), "r"((a).z), "r"((a).w), \
          "r"((b).x), "r"((b).y))

#define CP16(sa, gp) \
    asm volatile("cp.async.cg.shared.global [%0], [%1], 16;" :: "r"(sa), "l"(gp))
#define CP_COMMIT() asm volatile("cp.async.commit_group;" ::: "memory")
#define CP_WAIT1()  asm volatile("cp.async.wait_group 1;" ::: "memory")
#define CP_WAIT0()  asm volatile("cp.async.wait_group 0;" ::: "memory")

__device__ __forceinline__ uint32_t smem_u32(const void* p) {
    uint32_t a;
    asm("{ .reg .u64 t; cvta.to.shared.u64 t, %1; cvt.u32.u64 %0, t; }"
        : "=r"(a) : "l"(p));
    return a;
}

__device__ __forceinline__ void splitpack(float x, float y,
                                          uint32_t& hi, uint32_t& lo) {
    __nv_bfloat16 hx = __float2bfloat16(x);
    __nv_bfloat16 hy = __float2bfloat16(y);
    float lx = x - __bfloat162float(hx);
    float ly = y - __bfloat162float(hy);
    __nv_bfloat162 h2 = __halves2bfloat162(hx, hy);
    __nv_bfloat162 l2 = __floats2bfloat162_rn(lx, ly);
    hi = reinterpret_cast<uint32_t&>(h2);
    lo = reinterpret_cast<uint32_t&>(l2);
}

// fast e^x on the FMA pipe (poly exp2, rel err ~2e-6)
__device__ __forceinline__ float fast_exp(float x) {
    float y = x * 1.4426950408889634f;
    int ir = __float2int_rn(y);
    float f = (y - (float)ir) * 0.6931471805599453f;
    float p = 1.0f + f * (1.0f + f * (0.5f + f * (0.16666667f +
              f * (0.041666667f + f * 0.0083333333f))));
    return p * __int_as_float((ir + 127) << 23);
}

// ---------------- a2 = Wk^T bq ----------------
__global__ void a2_kernel(const float* __restrict__ Wk,
                          const float* __restrict__ bq) {
    int d = threadIdx.x;
    float s = 0.0f;
    for (int f = 0; f < 384; f++) s += Wk[(size_t)f * 384 + d] * bq[f];
    g_a2[d] = s;
}

// -------- presplit z (tiled, coalesced): offA + offB tiles + v = z.a2 ------
__global__ __launch_bounds__(256) void presplit_z(const float* __restrict__ z) {
    __shared__ __align__(16) uint32_t st[8192];   // 32KB staging
    const int tid = threadIdx.x;
    const int rt = blockIdx.x;                    // 0..767 row tile
    const int rl = tid >> 1;                      // local row 0..127
    const int half = tid & 1;
    const int row = (rt << 7) + rl;
    float vpart = 0.0f;

    for (int kt = 0; kt < 12; kt++) {
        const float* zp = z + (size_t)row * 384 + kt * 32 + half * 16;
        float vbuf[16];
        *(float4*)&vbuf[0]  = *(const float4*)(zp);
        *(float4*)&vbuf[4]  = *(const float4*)(zp + 4);
        *(float4*)&vbuf[8]  = *(const float4*)(zp + 8);
        *(float4*)&vbuf[12] = *(const float4*)(zp + 12);

        const float* ap = g_a2 + kt * 32 + half * 16;
        float abuf[16];
        *(float4*)&abuf[0]  = *(const float4*)(ap);
        *(float4*)&abuf[4]  = *(const float4*)(ap + 4);
        *(float4*)&abuf[8]  = *(const float4*)(ap + 8);
        *(float4*)&abuf[12] = *(const float4*)(ap + 12);
#pragma unroll
        for (int c = 0; c < 16; c++) vpart += vbuf[c] * abuf[c];

#pragma unroll
        for (int p = 0; p < 8; p++) {
            uint32_t h, l;
            splitpack(vbuf[2 * p], vbuf[2 * p + 1], h, l);
            int pp = half * 8 + p;
            int oA = offA(rl, pp) >> 2;
            int oB = offB(rl, pp) >> 2;
            st[oA] = h; st[2048 + oA] = l;
            st[4096 + oB] = h; st[6144 + oB] = l;
        }
        __syncthreads();

        size_t tb = (size_t)(rt * 12 + kt) * TILE_U32;
        int o = tid * 4;
        *(uint4*)&g_zh[tb + o]         = *(uint4*)&st[o];
        *(uint4*)&g_zh[tb + 1024 + o]  = *(uint4*)&st[1024 + o];
        *(uint4*)&g_zl[tb + o]         = *(uint4*)&st[2048 + o];
        *(uint4*)&g_zl[tb + 1024 + o]  = *(uint4*)&st[3072 + o];
        *(uint4*)&g_zbh[tb + o]        = *(uint4*)&st[4096 + o];
        *(uint4*)&g_zbh[tb + 1024 + o] = *(uint4*)&st[5120 + o];
        *(uint4*)&g_zbl[tb + o]        = *(uint4*)&st[6144 + o];
        *(uint4*)&g_zbl[tb + 1024 + o] = *(uint4*)&st[7168 + o];
        __syncthreads();
    }
    vpart += __shfl_xor_sync(0xffffffffu, vpart, 1);
    if (half == 0) g_v[row] = vpart;
}

// -------- presplit weights (small; scatter acceptable) --------
__global__ __launch_bounds__(256) void presplit_weights(
    const float* __restrict__ Wq, const float* __restrict__ Wk,
    const float* __restrict__ Wv)
{
    const int which = blockIdx.y;
    const int idx = blockIdx.x * 256 + threadIdx.x;   // < 73728
    if (which == 0) {
        int d = idx / 192, fp = idx % 192;
        float x = Wq[(size_t)(2 * fp) * 384 + d];
        float y = Wq[(size_t)(2 * fp + 1) * 384 + d];
        uint32_t h, l; splitpack(x, y, h, l);
        size_t o = (size_t)((d >> 7) * 12 + (fp >> 4)) * TILE_U32 +
                   (offA(d & 127, fp & 15) >> 2);
        g_wqTh[o] = h; g_wqTl[o] = l;
    } else if (which == 1) {
        int e = idx / 192, fp = idx % 192;
        float x = Wk[(size_t)(2 * fp) * 384 + e];
        float y = Wk[(size_t)(2 * fp + 1) * 384 + e];
        uint32_t h, l; splitpack(x, y, h, l);
        size_t o = (size_t)((e >> 7) * 12 + (fp >> 4)) * TILE_U32 +
                   (offB(e & 127, fp & 15) >> 2);
        g_wkTh[o] = h; g_wkTl[o] = l;
    } else {
        int ng = idx / 192, kp = idx % 192;
        float2 vv = *(const float2*)&Wv[(size_t)ng * 384 + kp * 2];
        uint32_t h, l; splitpack(vv.x, vv.y, h, l);
        size_t o = (size_t)((ng >> 7) * 12 + (kp >> 4)) * TILE_U32 +
                   (offB(ng & 127, kp & 15) >> 2);
        g_wvh[o] = h; g_wvl[o] = l;
    }
}

// ---------------------------------------------------------------------------
// MODE 0: Y & V projections grid(6,768)
// MODE 1: fused scores+exp -> P tiles + rowsums grid(6,256)
// MODE 2: out = (P V) / rowsum grid(3,3,256)
// MODE 3: A = Wq^T Wk grid(3,3)
// ---------------------------------------------------------------------------
template <int MODE>
__global__ __launch_bounds__(NTH, 2) void gemm(
    const float* __restrict__ bias, float* __restrict__ outp)
{
    extern __shared__ __align__(16) char sm[];
    const uint32_t smb = smem_u32(sm);
    const int tid = threadIdx.x;
    const int lane = tid & 31;
    const int wid = tid >> 5;
    const int wm = wid >> 2;
    const int wn = wid & 3;

    const uint32_t *Ah, *Al, *Bh, *Bl;
    int NKT, n0 = 0, m0 = 0, w = 0, mt = 0, b = 0;

    if (MODE == 0) {
        w = blockIdx.x / 3;                 // 0 = Y, 1 = V
        int nt = blockIdx.x % 3;
        n0 = nt * 128;
        Ah = g_zh + (size_t)blockIdx.y * 24576;
        Al = g_zl + (size_t)blockIdx.y * 24576;
        if (w == 0) { Bh = g_Abh + nt * 12 * TILE_U32; Bl = g_Abl + nt * 12 * TILE_U32; }
        else        { Bh = g_wvh + nt * 12 * TILE_U32; Bl = g_wvl + nt * 12 * TILE_U32; }
        NKT = 12;
    } else if (MODE == 1) {
        const int mtab[6] = {0, 1, 1, 2, 2, 2};
        const int ntab[6] = {0, 0, 1, 0, 1, 2};
        mt = mtab[blockIdx.x];
        int nt = ntab[blockIdx.x];
        b = blockIdx.y;
        m0 = mt * 128; n0 = nt * 128;
        Ah = g_Yh + (size_t)(b * 3 + mt) * 24576;
        Al = g_Yl + (size_t)(b * 3 + mt) * 24576;
        Bh = g_zbh + (size_t)(b * 3 + nt) * 24576;
        Bl = g_zbl + (size_t)(b * 3 + nt) * 24576;
        NKT = 12;
    } else if (MODE == 2) {
        int nt = blockIdx.x; mt = blockIdx.y; b = blockIdx.z;
        m0 = mt * 128; n0 = nt * 128;
        Ah = g_Ph + (size_t)(b * 3 + mt) * 24576;
        Al = g_Pl + (size_t)(b * 3 + mt) * 24576;
        Bh = g_Vth + (size_t)(b * 3 + nt) * 24576;
        Bl = g_Vtl + (size_t)(b * 3 + nt) * 24576;
        NKT = (mt + 1) * 4;
    } else {
        int nt = blockIdx.x; mt = blockIdx.y;
        m0 = mt * 128; n0 = nt * 128;
        Ah = g_wqTh + (size_t)mt * 24576;
        Al = g_wqTl + (size_t)mt * 24576;
        Bh = g_wkTh + (size_t)nt * 24576;
        Bl = g_wkTl + (size_t)nt * 24576;
        NKT = 12;
    }

    auto issue = [&](int kt, int st) {
        const uint32_t d0 = smb + st * STAGE_BYTES + tid * 16;
        const int go = kt * TILE_U32 + tid * 4;
        CP16(d0,              Ah + go);  CP16(d0 + 4096,          Ah + go + 1024);
        CP16(d0 + 8192,       Al + go);  CP16(d0 + 8192 + 4096,   Al + go + 1024);
        CP16(d0 + 16384,      Bh + go);  CP16(d0 + 16384 + 4096,  Bh + go + 1024);
        CP16(d0 + 24576,      Bl + go);  CP16(d0 + 24576 + 4096,  Bl + go + 1024);
    };

    issue(0, 0); CP_COMMIT();
    issue(1, 1); CP_COMMIT();

    float acc[4][4][4];
#pragma unroll
    for (int i = 0; i < 4; i++)
#pragma unroll
        for (int j = 0; j < 4; j++)
#pragma unroll
            for (int r = 0; r < 4; r++) acc[i][j][r] = 0.0f;

    int cs = 0, is = 2;
    for (int kt = 0; kt < NKT; kt++) {
        CP_WAIT1();
        __syncthreads();
        if (kt + 2 < NKT) issue(kt + 2, is);
        CP_COMMIT();

        const char* base = sm + cs * STAGE_BYTES;
#pragma unroll
        for (int s = 0; s < 2; s++) {
            uint4 ah[4], al[4];
#pragma unroll
            for (int i = 0; i < 4; i++) {
                int off = s * 4096 + (wm * 4 + i) * 512 + lane * 16;
                ah[i] = *(const uint4*)(base + off);
                al[i] = *(const uint4*)(base + 8192 + off);
            }
#pragma unroll
            for (int j = 0; j < 4; j++) {
                int off = s * 4096 + (wn * 4 + j) * 256 + lane * 8;
                uint2 bh = *(const uint2*)(base + 16384 + off);
                uint2 bl = *(const uint2*)(base + 24576 + off);
#pragma unroll
                for (int i = 0; i < 4; i++) MMA(acc[i][j], ah[i], bh);
#pragma unroll
                for (int i = 0; i < 4; i++) MMA(acc[i][j], ah[i], bl);
#pragma unroll
                for (int i = 0; i < 4; i++) MMA(acc[i][j], al[i], bh);
            }
        }
        cs = (cs == 2) ? 0 : cs + 1;
        is = (is == 2) ? 0 : is + 1;
    }

    // ---- epilogues ----
    const int g = lane >> 2, t = lane & 3;

    if (MODE == 0 && w == 0) {
        // Y: stage fragment tile in smem, coalesced write
        CP_WAIT0();
        __syncthreads();
        uint32_t* sp = (uint32_t*)sm;   // hi 32KB, lo at +8192 u32
#pragma unroll
        for (int i = 0; i < 4; i++) {
            const int rl = wm * 64 + i * 16 + g;
#pragma unroll
            for (int j = 0; j < 4; j++) {
                const int c0 = n0 + wn * 32 + j * 8 + t * 2;
                uint32_t h0, l0, h1, l1;
                splitpack(acc[i][j][0], acc[i][j][1], h0, l0);
                splitpack(acc[i][j][2], acc[i][j][3], h1, l1);
                int kp = (c0 - n0) >> 1;
                int sub = kp >> 4, kpp = kp & 15;
                int o1 = (sub * 8192 + offA(rl, kpp)) >> 2;
                int o2 = (sub * 8192 + offA(rl + 8, kpp)) >> 2;
                sp[o1] = h0; sp[8192 + o1] = l0;
                sp[o2] = h1; sp[8192 + o2] = l1;
            }
        }
        __syncthreads();
        size_t gb = ((size_t)blockIdx.y * 12 + (n0 >> 5)) * TILE_U32;
#pragma unroll
        for (int s4 = 0; s4 < 4; s4++) {
#pragma unroll
            for (int it = 0; it < 2; it++) {
                int o = it * 1024 + tid * 4;
                *(uint4*)&g_Yh[gb + s4 * 2048 + o] = *(const uint4*)&sp[s4 * 2048 + o];
                *(uint4*)&g_Yl[gb + s4 * 2048 + o] = *(const uint4*)&sp[8192 + s4 * 2048 + o];
            }
        }
    } else if (MODE == 0) {
        // V: fp32 transpose staging, then per-subtile fragment staging + coalesced
        CP_WAIT0();
        __syncthreads();
        float* s = (float*)sm;   // [128][132] = 67.6KB
#pragma unroll
        for (int i = 0; i < 4; i++) {
            const int rl = wm * 64 + i * 16 + g;
#pragma unroll
            for (int j = 0; j < 4; j++) {
                const int c = wn * 32 + j * 8 + t * 2;
                float b0 = bias[n0 + c], b1 = bias[n0 + c + 1];
                s[rl * 132 + c]           = acc[i][j][0] + b0;
                s[rl * 132 + c + 1]       = acc[i][j][1] + b1;
                s[(rl + 8) * 132 + c]     = acc[i][j][2] + b0;
                s[(rl + 8) * 132 + c + 1] = acc[i][j][3] + b1;
            }
        }
        __syncthreads();
        uint32_t* fh = (uint32_t*)(sm + 69632);   // 8KB
        uint32_t* fl = (uint32_t*)(sm + 77824);   // 8KB
        const int bb = blockIdx.y / 3;
        const int l0tok = (blockIdx.y % 3) * 128;
        const int dl = tid & 127;
        const int pb = (tid >> 7) * 8;
#pragma unroll
        for (int sub = 0; sub < 4; sub++) {
            int tb = sub * 32;
#pragma unroll
            for (int pp = 0; pp < 8; pp++) {
                int p = pb + pp;
                float x = s[(tb + 2 * p) * 132 + dl];
                float y = s[(tb + 2 * p + 1) * 132 + dl];
                uint32_t h, l;
                splitpack(x, y, h, l);
                int o = offB(dl, p) >> 2;
                fh[o] = h; fl[o] = l;
            }
            __syncthreads();
            int tok0 = l0tok + tb;
            size_t tile = (size_t)((bb * 3 + (n0 >> 7)) * 12 + (tok0 >> 5)) * TILE_U32;
            int o = tid * 4;
            *(uint4*)&g_Vth[tile + o]        = *(const uint4*)&fh[o];
            *(uint4*)&g_Vth[tile + 1024 + o] = *(const uint4*)&fh[1024 + o];
            *(uint4*)&g_Vtl[tile + o]        = *(const uint4*)&fl[o];
            *(uint4*)&g_Vtl[tile + 1024 + o] = *(const uint4*)&fl[1024 + o];
            __syncthreads();
        }
    } else if (MODE == 1) {
        // fused: mask + exp (unnormalized) + rowsums + coalesced P tiles
        CP_WAIT0();
        __syncthreads();
        uint32_t* sp = (uint32_t*)sm;           // staging: hi 32KB, lo 32KB
        float* rs4 = (float*)(sm + 65536);      // [4][128]
        float* vsm = (float*)(sm + 67584);      // [128]
        if (tid < 128) vsm[tid] = g_v[(size_t)b * 384 + n0 + tid];
        __syncthreads();

        float rsum[4][2];
#pragma unroll
        for (int i = 0; i < 4; i++) { rsum[i][0] = 0.0f; rsum[i][1] = 0.0f; }

#pragma unroll
        for (int i = 0; i < 4; i++) {
            const int rl = wm * 64 + i * 16 + g;
            const int q0 = m0 + rl, q1 = q0 + 8;
#pragma unroll
            for (int j = 0; j < 4; j++) {
                const int c0 = n0 + wn * 32 + j * 8 + t * 2;
                const int cl = c0 - n0;
                float vk0 = vsm[cl], vk1 = vsm[cl + 1];
                float p0 = (c0     <= q0) ? fast_exp((acc[i][j][0] + vk0) * INV_SQRT_D) : 0.0f;
                float p1 = (c0 + 1 <= q0) ? fast_exp((acc[i][j][1] + vk1) * INV_SQRT_D) : 0.0f;
                float p2 = (c0     <= q1) ? fast_exp((acc[i][j][2] + vk0) * INV_SQRT_D) : 0.0f;
                float p3 = (c0 + 1 <= q1) ? fast_exp((acc[i][j][3] + vk1) * INV_SQRT_D) : 0.0f;
                rsum[i][0] += p0 + p1;
                rsum[i][1] += p2 + p3;
                uint32_t h0, l0, h1, l1;
                splitpack(p0, p1, h0, l0);
                splitpack(p2, p3, h1, l1);
                int kp = cl >> 1;
                int sub = kp >> 4, kpp = kp & 15;
                int o1 = (sub * 8192 + offA(rl, kpp)) >> 2;
                int o2 = (sub * 8192 + offA(rl + 8, kpp)) >> 2;
                sp[o1] = h0; sp[8192 + o1] = l0;
                sp[o2] = h1; sp[8192 + o2] = l1;
            }
        }
#pragma unroll
        for (int i = 0; i < 4; i++) {
#pragma unroll
            for (int h = 0; h < 2; h++) {
                rsum[i][h] += __shfl_xor_sync(0xffffffffu, rsum[i][h], 1);
                rsum[i][h] += __shfl_xor_sync(0xffffffffu, rsum[i][h], 2);
            }
        }
        if (t == 0) {
#pragma unroll
            for (int i = 0; i < 4; i++) {
                int rl = wm * 64 + i * 16 + g;
                rs4[wn * 128 + rl]     = rsum[i][0];
                rs4[wn * 128 + rl + 8] = rsum[i][1];
            }
        }
        __syncthreads();
        size_t gbase = ((size_t)(b * 3 + mt) * 12 + (n0 >> 5)) * TILE_U32;
#pragma unroll
        for (int s4 = 0; s4 < 4; s4++) {
            size_t tb = gbase + s4 * TILE_U32;
#pragma unroll
            for (int it = 0; it < 2; it++) {
                int o = it * 1024 + tid * 4;
                *(uint4*)&g_Ph[tb + o] = *(const uint4*)&sp[s4 * 2048 + o];
                *(uint4*)&g_Pl[tb + o] = *(const uint4*)&sp[8192 + s4 * 2048 + o];
            }
        }
        if (tid < 128) {
            float ssum = rs4[tid] + rs4[128 + tid] + rs4[256 + tid] + rs4[384 + tid];
            g_rsp[(size_t)(n0 >> 7) * 98304 + (size_t)b * 384 + m0 + tid] = ssum;
        }
    } else if (MODE == 2) {
        float* Oo = outp + (size_t)b * BSTRIDE;
#pragma unroll
        for (int i = 0; i < 4; i++) {
            const int r0 = m0 + wm * 64 + i * 16 + g;
            float s0 = 0.0f, s1 = 0.0f;
            for (int k = 0; k <= mt; k++) {
                s0 += g_rsp[(size_t)k * 98304 + (size_t)b * 384 + r0];
                s1 += g_rsp[(size_t)k * 98304 + (size_t)b * 384 + r0 + 8];
            }
            float inv0 = 1.0f / s0, inv1 = 1.0f / s1;
#pragma unroll
            for (int j = 0; j < 4; j++) {
                const int c0 = n0 + wn * 32 + j * 8 + t * 2;
                *(float2*)&Oo[(size_t)r0 * 384 + c0] =
                    make_float2(acc[i][j][0] * inv0, acc[i][j][1] * inv0);
                *(float2*)&Oo[(size_t)(r0 + 8) * 384 + c0] =
                    make_float2(acc[i][j][2] * inv1, acc[i][j][3] * inv1);
            }
        }
    } else {
        // MODE 3: A[d,e] -> transpose-write g_Ab as offB (tiny; scatter ok)
        CP_WAIT0();
        __syncthreads();
        float* s = (float*)sm;   // [128 d][132 e]
#pragma unroll
        for (int i = 0; i < 4; i++) {
            const int rl = wm * 64 + i * 16 + g;
#pragma unroll
            for (int j = 0; j < 4; j++) {
                const int c = wn * 32 + j * 8 + t * 2;
                s[rl * 132 + c]           = acc[i][j][0];
                s[rl * 132 + c + 1]       = acc[i][j][1];
                s[(rl + 8) * 132 + c]     = acc[i][j][2];
                s[(rl + 8) * 132 + c + 1] = acc[i][j][3];
            }
        }
        __syncthreads();
#pragma unroll
        for (int it = 0; it < 8; it++) {
            int idx = it * 256 + tid;
            int el = idx & 127;
            int db = (idx >> 7) * 8;
            float v[8];
#pragma unroll
            for (int u = 0; u < 8; u++) v[u] = s[(db + u) * 132 + el];
            int k0 = m0 + db;
            size_t tile = (size_t)((n0 >> 7) * 12 + (k0 >> 5)) * TILE_U32;
            int p0 = (k0 & 31) >> 1;
#pragma unroll
            for (int pp = 0; pp < 4; pp++) {
                uint32_t h, l;
                splitpack(v[2 * pp], v[2 * pp + 1], h, l);
                size_t o = tile + (offB(el, p0 + pp) >> 2);
                g_Abh[o] = h; g_Abl[o] = l;
            }
        }
    }
}

// ---------------------------------------------------------------------------
extern "C" void kernel_launch(void* const* d_in, const int* in_sizes, int n_in,
                              void* d_out, int out_size)
{
    const float* z  = (const float*)d_in[0];
    const float* Wq = (const float*)d_in[1];
    const float* bq = (const float*)d_in[2];
    const float* Wk = (const float*)d_in[3];
    const float* Wv = (const float*)d_in[5];
    const float* bv = (const float*)d_in[6];
    float* out = (float*)d_out;

    cudaFuncSetAttribute(gemm<0>, cudaFuncAttributeMaxDynamicSharedMemorySize, SMEM_BYTES);
    cudaFuncSetAttribute(gemm<1>, cudaFuncAttributeMaxDynamicSharedMemorySize, SMEM_BYTES);
    cudaFuncSetAttribute(gemm<2>, cudaFuncAttributeMaxDynamicSharedMemorySize, SMEM_BYTES);
    cudaFuncSetAttribute(gemm<3>, cudaFuncAttributeMaxDynamicSharedMemorySize, SMEM_BYTES);

    dim3 blk(NTH);

    a2_kernel<<<1, 384>>>(Wk, bq);
    presplit_z<<<768, blk>>>(z);
    presplit_weights<<<dim3(288, 3), blk>>>(Wq, Wk, Wv);

    // A = Wq^T Wk (tiny)
    gemm<3><<<dim3(3, 3), blk, SMEM_BYTES>>>(nullptr, nullptr);

    // Y = z A (offA, staged) and V = z Wv^T + bv (offB transposed, staged)
    gemm<0><<<dim3(6, 768), blk, SMEM_BYTES>>>(bv, nullptr);

    // fused scores + exp -> P tiles + rowsum partials (lower triangle only)
    gemm<1><<<dim3(6, 256), blk, SMEM_BYTES>>>(nullptr, nullptr);

    // out = (P V) / rowsum
    gemm<2><<<dim3(3, 3, 256), blk, SMEM_BYTES>>>(nullptr, out);
}

// round 10
// speedup vs baseline: 1.4507x; 1.0467x over previous
#include <cuda_runtime.h>
#include <cuda_bf16.h>
#include <stdint.h>

#define NTH 256
#define BSTRIDE 147456               // floats per batch (384*384)
static const float INV_SQRT_D = 0.05103103630798288f;

#define NPAIR 18874368               // 256*384*192
#define TILE_U32 2048                // uint32 per 128x32 fragment tile (8KB)
#define WTILES (36 * TILE_U32)

// fragment-ordered 128x32 operand tiles
__device__ uint32_t g_zh[NPAIR],  g_zl[NPAIR];    // z, offA (A-op; also B via uint4 trick)
__device__ uint32_t g_Yh[NPAIR],  g_Yl[NPAIR];    // Y = z*(Wq^T Wk), offA
__device__ uint32_t g_Vth[NPAIR], g_Vtl[NPAIR];   // V transposed, offB
__device__ uint32_t g_Ph[NPAIR],  g_Pl[NPAIR];    // exp(scores), offA
__device__ uint32_t g_wqTh[WTILES], g_wqTl[WTILES];  // Wq^T, offA
__device__ uint32_t g_wkTh[WTILES], g_wkTl[WTILES];  // Wk^T, offB
__device__ uint32_t g_wvh[WTILES],  g_wvl[WTILES];   // Wv rows, offB
__device__ uint32_t g_Abh[WTILES],  g_Abl[WTILES];   // A=Wq^T Wk, offB
__device__ float    g_a2[384];                       // Wk^T bq
__device__ float    g_v[98304];                      // z . a2
__device__ float    g_rsp[3 * 98304];                // per-kt row partial sums

#define NSTAGE 3
#define STAGE_BYTES 32768            // A_HI 8K | A_LO 8K | B_HI 8K | B_LO 8K
#define SMEM_BYTES (NSTAGE * STAGE_BYTES)   // 96KB -> 2 CTAs/SM

__device__ __forceinline__ int offA(int r, int p) {
    return ((p >> 3) << 12) + ((r >> 4) << 9) +
           (((r & 7) * 4 + (p & 3)) << 4) +
           (((p >> 2) & 1) << 3) + (((r >> 3) & 1) << 2);
}
__device__ __forceinline__ int offB(int n, int p) {
    return ((p >> 3) << 12) + ((n >> 3) << 8) +
           (((n & 7) * 4 + (p & 3)) << 3) + (((p >> 2) & 1) << 2);
}

#define MMA(d, a, b) \
    asm volatile("mma.sync.aligned.m16n8k16.row.col.f32.bf16.bf16.f32 " \
        "{%0,%1,%2,%3},{%4,%5,%6,%7},{%8,%9},{%0,%1,%2,%3};" \
        : "+f"((d)[0]), "+f"((d)[1]), "+f"((d)[2]), "+f"((d)[3]) \
        : "r"((a).x), "r"((a).y), "r"((a).z), "r"((a).w), \
          "r"((b).x), "r"((b).y))

#define CP16(sa, gp) \
    asm volatile("cp.async.cg.shared.global [%0], [%1], 16;" :: "r"(sa), "l"(gp))
#define CP_COMMIT() asm volatile("cp.async.commit_group;" ::: "memory")
#define CP_WAIT1()  asm volatile("cp.async.wait_group 1;" ::: "memory")
#define CP_WAIT0()  asm volatile("cp.async.wait_group 0;" ::: "memory")

__device__ __forceinline__ uint32_t smem_u32(const void* p) {
    uint32_t a;
    asm("{ .reg .u64 t; cvta.to.shared.u64 t, %1; cvt.u32.u64 %0, t; }"
        : "=r"(a) : "l"(p));
    return a;
}

__device__ __forceinline__ void splitpack(float x, float y,
                                          uint32_t& hi, uint32_t& lo) {
    __nv_bfloat16 hx = __float2bfloat16(x);
    __nv_bfloat16 hy = __float2bfloat16(y);
    float lx = x - __bfloat162float(hx);
    float ly = y - __bfloat162float(hy);
    __nv_bfloat162 h2 = __halves2bfloat162(hx, hy);
    __nv_bfloat162 l2 = __floats2bfloat162_rn(lx, ly);
    hi = reinterpret_cast<uint32_t&>(h2);
    lo = reinterpret_cast<uint32_t&>(l2);
}

// fast e^x on the FMA pipe (poly exp2, rel err ~2e-6)
__device__ __forceinline__ float fast_exp(float x) {
    float y = x * 1.4426950408889634f;
    int ir = __float2int_rn(y);
    float f = (y - (float)ir) * 0.6931471805599453f;
    float p = 1.0f + f * (1.0f + f * (0.5f + f * (0.16666667f +
              f * (0.041666667f + f * 0.0083333333f))));
    return p * __int_as_float((ir + 127) << 23);
}

// ---------------- a2 = Wk^T bq ----------------
__global__ void a2_kernel(const float* __restrict__ Wk,
                          const float* __restrict__ bq) {
    int d = threadIdx.x;
    float s = 0.0f;
    for (int f = 0; f < 384; f++) s += Wk[(size_t)f * 384 + d] * bq[f];
    g_a2[d] = s;
}

// -------- presplit z (tiled, coalesced): offA tiles + v = z.a2 --------
__global__ __launch_bounds__(256) void presplit_z(const float* __restrict__ z) {
    __shared__ __align__(16) uint32_t st[4096];   // 16KB staging (hi | lo)
    const int tid = threadIdx.x;
    const int rt = blockIdx.x;                    // 0..767 row tile
    const int rl = tid >> 1;                      // local row 0..127
    const int half = tid & 1;
    const int row = (rt << 7) + rl;
    float vpart = 0.0f;

    for (int kt = 0; kt < 12; kt++) {
        const float* zp = z + (size_t)row * 384 + kt * 32 + half * 16;
        float vbuf[16];
        *(float4*)&vbuf[0]  = *(const float4*)(zp);
        *(float4*)&vbuf[4]  = *(const float4*)(zp + 4);
        *(float4*)&vbuf[8]  = *(const float4*)(zp + 8);
        *(float4*)&vbuf[12] = *(const float4*)(zp + 12);

        const float* ap = g_a2 + kt * 32 + half * 16;
        float abuf[16];
        *(float4*)&abuf[0]  = *(const float4*)(ap);
        *(float4*)&abuf[4]  = *(const float4*)(ap + 4);
        *(float4*)&abuf[8]  = *(const float4*)(ap + 8);
        *(float4*)&abuf[12] = *(const float4*)(ap + 12);
#pragma unroll
        for (int c = 0; c < 16; c++) vpart += vbuf[c] * abuf[c];

#pragma unroll
        for (int p = 0; p < 8; p++) {
            uint32_t h, l;
            splitpack(vbuf[2 * p], vbuf[2 * p + 1], h, l);
            int pp = half * 8 + p;
            int oA = offA(rl, pp) >> 2;
            st[oA] = h; st[2048 + oA] = l;
        }
        __syncthreads();

        size_t tb = (size_t)(rt * 12 + kt) * TILE_U32;
        int o = tid * 4;
        *(uint4*)&g_zh[tb + o]        = *(uint4*)&st[o];
        *(uint4*)&g_zh[tb + 1024 + o] = *(uint4*)&st[1024 + o];
        *(uint4*)&g_zl[tb + o]        = *(uint4*)&st[2048 + o];
        *(uint4*)&g_zl[tb + 1024 + o] = *(uint4*)&st[3072 + o];
        __syncthreads();
    }
    vpart += __shfl_xor_sync(0xffffffffu, vpart, 1);
    if (half == 0) g_v[row] = vpart;
}

// -------- presplit weights (small; scatter acceptable) --------
__global__ __launch_bounds__(256) void presplit_weights(
    const float* __restrict__ Wq, const float* __restrict__ Wk,
    const float* __restrict__ Wv)
{
    const int which = blockIdx.y;
    const int idx = blockIdx.x * 256 + threadIdx.x;   // < 73728
    if (which == 0) {
        int d = idx / 192, fp = idx % 192;
        float x = Wq[(size_t)(2 * fp) * 384 + d];
        float y = Wq[(size_t)(2 * fp + 1) * 384 + d];
        uint32_t h, l; splitpack(x, y, h, l);
        size_t o = (size_t)((d >> 7) * 12 + (fp >> 4)) * TILE_U32 +
                   (offA(d & 127, fp & 15) >> 2);
        g_wqTh[o] = h; g_wqTl[o] = l;
    } else if (which == 1) {
        int e = idx / 192, fp = idx % 192;
        float x = Wk[(size_t)(2 * fp) * 384 + e];
        float y = Wk[(size_t)(2 * fp + 1) * 384 + e];
        uint32_t h, l; splitpack(x, y, h, l);
        size_t o = (size_t)((e >> 7) * 12 + (fp >> 4)) * TILE_U32 +
                   (offB(e & 127, fp & 15) >> 2);
        g_wkTh[o] = h; g_wkTl[o] = l;
    } else {
        int ng = idx / 192, kp = idx % 192;
        float2 vv = *(const float2*)&Wv[(size_t)ng * 384 + kp * 2];
        uint32_t h, l; splitpack(vv.x, vv.y, h, l);
        size_t o = (size_t)((ng >> 7) * 12 + (kp >> 4)) * TILE_U32 +
                   (offB(ng & 127, kp & 15) >> 2);
        g_wvh[o] = h; g_wvl[o] = l;
    }
}

// ---------------------------------------------------------------------------
// MODE 0: Y & V projections grid(6,768)
// MODE 1: fused scores+exp -> P tiles + rowsums grid(6,256); B = z offA tiles
// MODE 2: out = (P V) / rowsum grid(3,3,256)
// MODE 3: A = Wq^T Wk grid(3,3)
// ---------------------------------------------------------------------------
template <int MODE>
__global__ __launch_bounds__(NTH, 2) void gemm(
    const float* __restrict__ bias, float* __restrict__ outp)
{
    extern __shared__ __align__(16) char sm[];
    const uint32_t smb = smem_u32(sm);
    const int tid = threadIdx.x;
    const int lane = tid & 31;
    const int wid = tid >> 5;
    const int wm = wid >> 2;
    const int wn = wid & 3;

    const uint32_t *Ah, *Al, *Bh, *Bl;
    int NKT, n0 = 0, m0 = 0, w = 0, mt = 0, b = 0;

    if (MODE == 0) {
        w = blockIdx.x / 3;                 // 0 = Y, 1 = V
        int nt = blockIdx.x % 3;
        n0 = nt * 128;
        Ah = g_zh + (size_t)blockIdx.y * 24576;
        Al = g_zl + (size_t)blockIdx.y * 24576;
        if (w == 0) { Bh = g_Abh + nt * 12 * TILE_U32; Bl = g_Abl + nt * 12 * TILE_U32; }
        else        { Bh = g_wvh + nt * 12 * TILE_U32; Bl = g_wvl + nt * 12 * TILE_U32; }
        NKT = 12;
    } else if (MODE == 1) {
        const int mtab[6] = {0, 1, 1, 2, 2, 2};
        const int ntab[6] = {0, 0, 1, 0, 1, 2};
        mt = mtab[blockIdx.x];
        int nt = ntab[blockIdx.x];
        b = blockIdx.y;
        m0 = mt * 128; n0 = nt * 128;
        Ah = g_Yh + (size_t)(b * 3 + mt) * 24576;
        Al = g_Yl + (size_t)(b * 3 + mt) * 24576;
        Bh = g_zh + (size_t)(b * 3 + nt) * 24576;   // z offA tiles as B
        Bl = g_zl + (size_t)(b * 3 + nt) * 24576;
        NKT = 12;
    } else if (MODE == 2) {
        int nt = blockIdx.x; mt = blockIdx.y; b = blockIdx.z;
        m0 = mt * 128; n0 = nt * 128;
        Ah = g_Ph + (size_t)(b * 3 + mt) * 24576;
        Al = g_Pl + (size_t)(b * 3 + mt) * 24576;
        Bh = g_Vth + (size_t)(b * 3 + nt) * 24576;
        Bl = g_Vtl + (size_t)(b * 3 + nt) * 24576;
        NKT = (mt + 1) * 4;
    } else {
        int nt = blockIdx.x; mt = blockIdx.y;
        m0 = mt * 128; n0 = nt * 128;
        Ah = g_wqTh + (size_t)mt * 24576;
        Al = g_wqTl + (size_t)mt * 24576;
        Bh = g_wkTh + (size_t)nt * 24576;
        Bl = g_wkTl + (size_t)nt * 24576;
        NKT = 12;
    }

    auto issue = [&](int kt, int st) {
        const uint32_t d0 = smb + st * STAGE_BYTES + tid * 16;
        const int go = kt * TILE_U32 + tid * 4;
        CP16(d0,              Ah + go);  CP16(d0 + 4096,          Ah + go + 1024);
        CP16(d0 + 8192,       Al + go);  CP16(d0 + 8192 + 4096,   Al + go + 1024);
        CP16(d0 + 16384,      Bh + go);  CP16(d0 + 16384 + 4096,  Bh + go + 1024);
        CP16(d0 + 24576,      Bl + go);  CP16(d0 + 24576 + 4096,  Bl + go + 1024);
    };

    issue(0, 0); CP_COMMIT();
    issue(1, 1); CP_COMMIT();

    float acc[4][4][4];
#pragma unroll
    for (int i = 0; i < 4; i++)
#pragma unroll
        for (int j = 0; j < 4; j++)
#pragma unroll
            for (int r = 0; r < 4; r++) acc[i][j][r] = 0.0f;

    int cs = 0, is = 2;
    for (int kt = 0; kt < NKT; kt++) {
        CP_WAIT1();
        __syncthreads();
        if (kt + 2 < NKT) issue(kt + 2, is);
        CP_COMMIT();

        const char* base = sm + cs * STAGE_BYTES;
#pragma unroll
        for (int s = 0; s < 2; s++) {
            uint4 ah[4], al[4];
#pragma unroll
            for (int i = 0; i < 4; i++) {
                int off = s * 4096 + (wm * 4 + i) * 512 + lane * 16;
                ah[i] = *(const uint4*)(base + off);
                al[i] = *(const uint4*)(base + 8192 + off);
            }
            if (MODE == 1) {
                // B tiles are offA layout: one uint4 = two n8k16 B fragments
#pragma unroll
                for (int jj = 0; jj < 2; jj++) {
                    int off = s * 4096 + (wn * 2 + jj) * 512 + lane * 16;
                    uint4 bhv = *(const uint4*)(base + 16384 + off);
                    uint4 blv = *(const uint4*)(base + 24576 + off);
                    uint2 bh0 = make_uint2(bhv.x, bhv.z);
                    uint2 bh1 = make_uint2(bhv.y, bhv.w);
                    uint2 bl0 = make_uint2(blv.x, blv.z);
                    uint2 bl1 = make_uint2(blv.y, blv.w);
                    const int j0 = jj * 2, j1 = jj * 2 + 1;
#pragma unroll
                    for (int i = 0; i < 4; i++) MMA(acc[i][j0], ah[i], bh0);
#pragma unroll
                    for (int i = 0; i < 4; i++) MMA(acc[i][j1], ah[i], bh1);
#pragma unroll
                    for (int i = 0; i < 4; i++) MMA(acc[i][j0], ah[i], bl0);
#pragma unroll
                    for (int i = 0; i < 4; i++) MMA(acc[i][j1], ah[i], bl1);
#pragma unroll
                    for (int i = 0; i < 4; i++) MMA(acc[i][j0], al[i], bh0);
#pragma unroll
                    for (int i = 0; i < 4; i++) MMA(acc[i][j1], al[i], bh1);
                }
            } else {
#pragma unroll
                for (int j = 0; j < 4; j++) {
                    int off = s * 4096 + (wn * 4 + j) * 256 + lane * 8;
                    uint2 bh = *(const uint2*)(base + 16384 + off);
                    uint2 bl = *(const uint2*)(base + 24576 + off);
#pragma unroll
                    for (int i = 0; i < 4; i++) MMA(acc[i][j], ah[i], bh);
#pragma unroll
                    for (int i = 0; i < 4; i++) MMA(acc[i][j], ah[i], bl);
#pragma unroll
                    for (int i = 0; i < 4; i++) MMA(acc[i][j], al[i], bh);
                }
            }
        }
        cs = (cs == 2) ? 0 : cs + 1;
        is = (is == 2) ? 0 : is + 1;
    }

    // ---- epilogues ----
    const int g = lane >> 2, t = lane & 3;

    if (MODE == 0 && w == 0) {
        // Y: stage fragment tile in smem, coalesced write
        CP_WAIT0();
        __syncthreads();
        uint32_t* sp = (uint32_t*)sm;   // hi 32KB, lo at +8192 u32
#pragma unroll
        for (int i = 0; i < 4; i++) {
            const int rl = wm * 64 + i * 16 + g;
#pragma unroll
            for (int j = 0; j < 4; j++) {
                const int c0 = n0 + wn * 32 + j * 8 + t * 2;
                uint32_t h0, l0, h1, l1;
                splitpack(acc[i][j][0], acc[i][j][1], h0, l0);
                splitpack(acc[i][j][2], acc[i][j][3], h1, l1);
                int kp = (c0 - n0) >> 1;
                int sub = kp >> 4, kpp = kp & 15;
                int o1 = (sub * 8192 + offA(rl, kpp)) >> 2;
                int o2 = (sub * 8192 + offA(rl + 8, kpp)) >> 2;
                sp[o1] = h0; sp[8192 + o1] = l0;
                sp[o2] = h1; sp[8192 + o2] = l1;
            }
        }
        __syncthreads();
        size_t gb = ((size_t)blockIdx.y * 12 + (n0 >> 5)) * TILE_U32;
#pragma unroll
        for (int s4 = 0; s4 < 4; s4++) {
#pragma unroll
            for (int it = 0; it < 2; it++) {
                int o = it * 1024 + tid * 4;
                *(uint4*)&g_Yh[gb + s4 * 2048 + o] = *(const uint4*)&sp[s4 * 2048 + o];
                *(uint4*)&g_Yl[gb + s4 * 2048 + o] = *(const uint4*)&sp[8192 + s4 * 2048 + o];
            }
        }
    } else if (MODE == 0) {
        // V: fp32 transpose staging, then per-subtile fragment staging + coalesced
        CP_WAIT0();
        __syncthreads();
        float* s = (float*)sm;   // [128][132]
#pragma unroll
        for (int i = 0; i < 4; i++) {
            const int rl = wm * 64 + i * 16 + g;
#pragma unroll
            for (int j = 0; j < 4; j++) {
                const int c = wn * 32 + j * 8 + t * 2;
                float b0 = bias[n0 + c], b1 = bias[n0 + c + 1];
                s[rl * 132 + c]           = acc[i][j][0] + b0;
                s[rl * 132 + c + 1]       = acc[i][j][1] + b1;
                s[(rl + 8) * 132 + c]     = acc[i][j][2] + b0;
                s[(rl + 8) * 132 + c + 1] = acc[i][j][3] + b1;
            }
        }
        __syncthreads();
        uint32_t* fh = (uint32_t*)(sm + 69632);   // 8KB
        uint32_t* fl = (uint32_t*)(sm + 77824);   // 8KB
        const int bb = blockIdx.y / 3;
        const int l0tok = (blockIdx.y % 3) * 128;
        const int dl = tid & 127;
        const int pb = (tid >> 7) * 8;
#pragma unroll
        for (int sub = 0; sub < 4; sub++) {
            int tb = sub * 32;
#pragma unroll
            for (int pp = 0; pp < 8; pp++) {
                int p = pb + pp;
                float x = s[(tb + 2 * p) * 132 + dl];
                float y = s[(tb + 2 * p + 1) * 132 + dl];
                uint32_t h, l;
                splitpack(x, y, h, l);
                int o = offB(dl, p) >> 2;
                fh[o] = h; fl[o] = l;
            }
            __syncthreads();
            int tok0 = l0tok + tb;
            size_t tile = (size_t)((bb * 3 + (n0 >> 7)) * 12 + (tok0 >> 5)) * TILE_U32;
            int o = tid * 4;
            *(uint4*)&g_Vth[tile + o]        = *(const uint4*)&fh[o];
            *(uint4*)&g_Vth[tile + 1024 + o] = *(const uint4*)&fh[1024 + o];
            *(uint4*)&g_Vtl[tile + o]        = *(const uint4*)&fl[o];
            *(uint4*)&g_Vtl[tile + 1024 + o] = *(const uint4*)&fl[1024 + o];
            __syncthreads();
        }
    } else if (MODE == 1) {
        // fused: mask + exp (unnormalized) + rowsums + coalesced P tiles
        CP_WAIT0();
        __syncthreads();
        uint32_t* sp = (uint32_t*)sm;           // staging: hi 32KB, lo 32KB
        float* rs4 = (float*)(sm + 65536);      // [4][128]
        float* vsm = (float*)(sm + 67584);      // [128]
        if (tid < 128) vsm[tid] = g_v[(size_t)b * 384 + n0 + tid];
        __syncthreads();

        float rsum[4][2];
#pragma unroll
        for (int i = 0; i < 4; i++) { rsum[i][0] = 0.0f; rsum[i][1] = 0.0f; }

#pragma unroll
        for (int i = 0; i < 4; i++) {
            const int rl = wm * 64 + i * 16 + g;
            const int q0 = m0 + rl, q1 = q0 + 8;
#pragma unroll
            for (int j = 0; j < 4; j++) {
                const int c0 = n0 + wn * 32 + j * 8 + t * 2;
                const int cl = c0 - n0;
                float vk0 = vsm[cl], vk1 = vsm[cl + 1];
                float p0 = (c0     <= q0) ? fast_exp((acc[i][j][0] + vk0) * INV_SQRT_D) : 0.0f;
                float p1 = (c0 + 1 <= q0) ? fast_exp((acc[i][j][1] + vk1) * INV_SQRT_D) : 0.0f;
                float p2 = (c0     <= q1) ? fast_exp((acc[i][j][2] + vk0) * INV_SQRT_D) : 0.0f;
                float p3 = (c0 + 1 <= q1) ? fast_exp((acc[i][j][3] + vk1) * INV_SQRT_D) : 0.0f;
                rsum[i][0] += p0 + p1;
                rsum[i][1] += p2 + p3;
                uint32_t h0, l0, h1, l1;
                splitpack(p0, p1, h0, l0);
                splitpack(p2, p3, h1, l1);
                int kp = cl >> 1;
                int sub = kp >> 4, kpp = kp & 15;
                int o1 = (sub * 8192 + offA(rl, kpp)) >> 2;
                int o2 = (sub * 8192 + offA(rl + 8, kpp)) >> 2;
                sp[o1] = h0; sp[8192 + o1] = l0;
                sp[o2] = h1; sp[8192 + o2] = l1;
            }
        }
#pragma unroll
        for (int i = 0; i < 4; i++) {
#pragma unroll
            for (int h = 0; h < 2; h++) {
                rsum[i][h] += __shfl_xor_sync(0xffffffffu, rsum[i][h], 1);
                rsum[i][h] += __shfl_xor_sync(0xffffffffu, rsum[i][h], 2);
            }
        }
        if (t == 0) {
#pragma unroll
            for (int i = 0; i < 4; i++) {
                int rl = wm * 64 + i * 16 + g;
                rs4[wn * 128 + rl]     = rsum[i][0];
                rs4[wn * 128 + rl + 8] = rsum[i][1];
            }
        }
        __syncthreads();
        size_t gbase = ((size_t)(b * 3 + mt) * 12 + (n0 >> 5)) * TILE_U32;
#pragma unroll
        for (int s4 = 0; s4 < 4; s4++) {
            size_t tb = gbase + s4 * TILE_U32;
#pragma unroll
            for (int it = 0; it < 2; it++) {
                int o = it * 1024 + tid * 4;
                *(uint4*)&g_Ph[tb + o] = *(const uint4*)&sp[s4 * 2048 + o];
                *(uint4*)&g_Pl[tb + o] = *(const uint4*)&sp[8192 + s4 * 2048 + o];
            }
        }
        if (tid < 128) {
            float ssum = rs4[tid] + rs4[128 + tid] + rs4[256 + tid] + rs4[384 + tid];
            g_rsp[(size_t)(n0 >> 7) * 98304 + (size_t)b * 384 + m0 + tid] = ssum;
        }
    } else if (MODE == 2) {
        float* Oo = outp + (size_t)b * BSTRIDE;
#pragma unroll
        for (int i = 0; i < 4; i++) {
            const int r0 = m0 + wm * 64 + i * 16 + g;
            float s0 = 0.0f, s1 = 0.0f;
            for (int k = 0; k <= mt; k++) {
                s0 += g_rsp[(size_t)k * 98304 + (size_t)b * 384 + r0];
                s1 += g_rsp[(size_t)k * 98304 + (size_t)b * 384 + r0 + 8];
            }
            float inv0 = 1.0f / s0, inv1 = 1.0f / s1;
#pragma unroll
            for (int j = 0; j < 4; j++) {
                const int c0 = n0 + wn * 32 + j * 8 + t * 2;
                *(float2*)&Oo[(size_t)r0 * 384 + c0] =
                    make_float2(acc[i][j][0] * inv0, acc[i][j][1] * inv0);
                *(float2*)&Oo[(size_t)(r0 + 8) * 384 + c0] =
                    make_float2(acc[i][j][2] * inv1, acc[i][j][3] * inv1);
            }
        }
    } else {
        // MODE 3: A[d,e] -> transpose-write g_Ab as offB (tiny; scatter ok)
        CP_WAIT0();
        __syncthreads();
        float* s = (float*)sm;   // [128 d][132 e]
#pragma unroll
        for (int i = 0; i < 4; i++) {
            const int rl = wm * 64 + i * 16 + g;
#pragma unroll
            for (int j = 0; j < 4; j++) {
                const int c = wn * 32 + j * 8 + t * 2;
                s[rl * 132 + c]           = acc[i][j][0];
                s[rl * 132 + c + 1]       = acc[i][j][1];
                s[(rl + 8) * 132 + c]     = acc[i][j][2];
                s[(rl + 8) * 132 + c + 1] = acc[i][j][3];
            }
        }
        __syncthreads();
#pragma unroll
        for (int it = 0; it < 8; it++) {
            int idx = it * 256 + tid;
            int el = idx & 127;
            int db = (idx >> 7) * 8;
            float v[8];
#pragma unroll
            for (int u = 0; u < 8; u++) v[u] = s[(db + u) * 132 + el];
            int k0 = m0 + db;
            size_t tile = (size_t)((n0 >> 7) * 12 + (k0 >> 5)) * TILE_U32;
            int p0 = (k0 & 31) >> 1;
#pragma unroll
            for (int pp = 0; pp < 4; pp++) {
                uint32_t h, l;
                splitpack(v[2 * pp], v[2 * pp + 1], h, l);
                size_t o = tile + (offB(el, p0 + pp) >> 2);
                g_Abh[o] = h; g_Abl[o] = l;
            }
        }
    }
}

// ---------------------------------------------------------------------------
extern "C" void kernel_launch(void* const* d_in, const int* in_sizes, int n_in,
                              void* d_out, int out_size)
{
    const float* z  = (const float*)d_in[0];
    const float* Wq = (const float*)d_in[1];
    const float* bq = (const float*)d_in[2];
    const float* Wk = (const float*)d_in[3];
    const float* Wv = (const float*)d_in[5];
    const float* bv = (const float*)d_in[6];
    float* out = (float*)d_out;

    cudaFuncSetAttribute(gemm<0>, cudaFuncAttributeMaxDynamicSharedMemorySize, SMEM_BYTES);
    cudaFuncSetAttribute(gemm<1>, cudaFuncAttributeMaxDynamicSharedMemorySize, SMEM_BYTES);
    cudaFuncSetAttribute(gemm<2>, cudaFuncAttributeMaxDynamicSharedMemorySize, SMEM_BYTES);
    cudaFuncSetAttribute(gemm<3>, cudaFuncAttributeMaxDynamicSharedMemorySize, SMEM_BYTES);

    dim3 blk(NTH);

    a2_kernel<<<1, 384>>>(Wk, bq);
    presplit_z<<<768, blk>>>(z);
    presplit_weights<<<dim3(288, 3), blk>>>(Wq, Wk, Wv);

    // A = Wq^T Wk (tiny)
    gemm<3><<<dim3(3, 3), blk, SMEM_BYTES>>>(nullptr, nullptr);

    // Y = z A (offA, staged) and V = z Wv^T + bv (offB transposed, staged)
    gemm<0><<<dim3(6, 768), blk, SMEM_BYTES>>>(bv, nullptr);

    // fused scores + exp -> P tiles + rowsum partials (lower triangle only)
    gemm<1><<<dim3(6, 256), blk, SMEM_BYTES>>>(nullptr, nullptr);

    // out = (P V) / rowsum
    gemm<2><<<dim3(3, 3, 256), blk, SMEM_BYTES>>>(nullptr, out);
}

// round 11
// speedup vs baseline: 1.8627x; 1.2840x over previous
#include <cuda_runtime.h>
#include <cuda_fp16.h>
#include <stdint.h>

#define NTH 256
#define BSTRIDE 147456               // floats per batch (384*384)
static const float INV_SQRT_D = 0.05103103630798288f;

#define NPAIR 18874368               // 256*384*192
#define TILE_U32 2048                // uint32 per 128x32 fragment tile (8KB)
#define WTILES (36 * TILE_U32)

// fragment-ordered 128x32 operand tiles (fp16 pairs)
__device__ uint32_t g_zh[NPAIR],  g_zl[NPAIR];    // z, offA (A-op; B via uint4 trick, hi only)
__device__ uint32_t g_Yh[NPAIR],  g_Yl[NPAIR];    // Y = z*(Wq^T Wk), offA (A-op)
__device__ uint32_t g_Vth[NPAIR];                 // V transposed, offB (B-op: hi only)
__device__ uint32_t g_Ph[NPAIR],  g_Pl[NPAIR];    // exp(scores), offA (A-op)
__device__ uint32_t g_wqTh[WTILES], g_wqTl[WTILES];  // Wq^T, offA (A-op)
__device__ uint32_t g_wkTh[WTILES];                  // Wk^T, offB (B-op)
__device__ uint32_t g_wvh[WTILES];                   // Wv rows, offB (B-op)
__device__ uint32_t g_Abh[WTILES];                   // A=Wq^T Wk, offB (B-op)
__device__ float    g_a2[384];                       // Wk^T bq
__device__ float    g_v[98304];                      // z . a2
__device__ float    g_rsp[3 * 98304];                // per-kt row partial sums

#define NSTAGE 3
#define STAGE_BYTES 24576            // A_HI 8K | A_LO 8K | B_HI 8K
#define SMEM_BYTES 77824             // 76KB -> 2 CTAs/SM

__device__ __forceinline__ int offA(int r, int p) {
    return ((p >> 3) << 12) + ((r >> 4) << 9) +
           (((r & 7) * 4 + (p & 3)) << 4) +
           (((p >> 2) & 1) << 3) + (((r >> 3) & 1) << 2);
}
__device__ __forceinline__ int offB(int n, int p) {
    return ((p >> 3) << 12) + ((n >> 3) << 8) +
           (((n & 7) * 4 + (p & 3)) << 3) + (((p >> 2) & 1) << 2);
}

#define MMA(d, a, b) \
    asm volatile("mma.sync.aligned.m16n8k16.row.col.f32.f16.f16.f32 " \
        "{%0,%1,%2,%3},{%4,%5,%6,%7},{%8,%9},{%0,%1,%2,%3};" \
        : "+f"((d)[0]), "+f"((d)[1]), "+f"((d)[2]), "+f"((d)[3]) \
        : "r"((a).x), "r"((a).y), "r"((a).z), "r"((a).w), \
          "r"((b).x), "r"((b).y))

#define CP16(sa, gp) \
    asm volatile("cp.async.cg.shared.global [%0], [%1], 16;" :: "r"(sa), "l"(gp))
#define CP_COMMIT() asm volatile("cp.async.commit_group;" ::: "memory")
#define CP_WAIT1()  asm volatile("cp.async.wait_group 1;" ::: "memory")
#define CP_WAIT0()  asm volatile("cp.async.wait_group 0;" ::: "memory")

__device__ __forceinline__ uint32_t smem_u32(const void* p) {
    uint32_t a;
    asm("{ .reg .u64 t; cvta.to.shared.u64 t, %1; cvt.u32.u64 %0, t; }"
        : "=r"(a) : "l"(p));
    return a;
}

// fp16 split: hi = fp16(x), lo = fp16(x - hi); packed as half2 pairs
__device__ __forceinline__ void splitpack(float x, float y,
                                          uint32_t& hi, uint32_t& lo) {
    __half hx = __float2half_rn(x);
    __half hy = __float2half_rn(y);
    float lx = x - __half2float(hx);
    float ly = y - __half2float(hy);
    __half2 h2 = __halves2half2(hx, hy);
    __half2 l2 = __floats2half2_rn(lx, ly);
    hi = reinterpret_cast<uint32_t&>(h2);
    lo = reinterpret_cast<uint32_t&>(l2);
}
__device__ __forceinline__ uint32_t packh2(float x, float y) {
    __half2 h2 = __floats2half2_rn(x, y);
    return reinterpret_cast<uint32_t&>(h2);
}

// fast e^x on the FMA pipe (poly exp2, rel err ~2e-6)
__device__ __forceinline__ float fast_exp(float x) {
    float y = x * 1.4426950408889634f;
    int ir = __float2int_rn(y);
    float f = (y - (float)ir) * 0.6931471805599453f;
    float p = 1.0f + f * (1.0f + f * (0.5f + f * (0.16666667f +
              f * (0.041666667f + f * 0.0083333333f))));
    return p * __int_as_float((ir + 127) << 23);
}

// ---------------- a2 = Wk^T bq ----------------
__global__ void a2_kernel(const float* __restrict__ Wk,
                          const float* __restrict__ bq) {
    int d = threadIdx.x;
    float s = 0.0f;
    for (int f = 0; f < 384; f++) s += Wk[(size_t)f * 384 + d] * bq[f];
    g_a2[d] = s;
}

// -------- presplit z (tiled, coalesced): offA tiles + v = z.a2 --------
__global__ __launch_bounds__(256) void presplit_z(const float* __restrict__ z) {
    __shared__ __align__(16) uint32_t st[4096];   // 16KB staging (hi | lo)
    const int tid = threadIdx.x;
    const int rt = blockIdx.x;                    // 0..767 row tile
    const int rl = tid >> 1;                      // local row 0..127
    const int half = tid & 1;
    const int row = (rt << 7) + rl;
    float vpart = 0.0f;

    for (int kt = 0; kt < 12; kt++) {
        const float* zp = z + (size_t)row * 384 + kt * 32 + half * 16;
        float vbuf[16];
        *(float4*)&vbuf[0]  = *(const float4*)(zp);
        *(float4*)&vbuf[4]  = *(const float4*)(zp + 4);
        *(float4*)&vbuf[8]  = *(const float4*)(zp + 8);
        *(float4*)&vbuf[12] = *(const float4*)(zp + 12);

        const float* ap = g_a2 + kt * 32 + half * 16;
        float abuf[16];
        *(float4*)&abuf[0]  = *(const float4*)(ap);
        *(float4*)&abuf[4]  = *(const float4*)(ap + 4);
        *(float4*)&abuf[8]  = *(const float4*)(ap + 8);
        *(float4*)&abuf[12] = *(const float4*)(ap + 12);
#pragma unroll
        for (int c = 0; c < 16; c++) vpart += vbuf[c] * abuf[c];

#pragma unroll
        for (int p = 0; p < 8; p++) {
            uint32_t h, l;
            splitpack(vbuf[2 * p], vbuf[2 * p + 1], h, l);
            int pp = half * 8 + p;
            int oA = offA(rl, pp) >> 2;
            st[oA] = h; st[2048 + oA] = l;
        }
        __syncthreads();

        size_t tb = (size_t)(rt * 12 + kt) * TILE_U32;
        int o = tid * 4;
        *(uint4*)&g_zh[tb + o]        = *(uint4*)&st[o];
        *(uint4*)&g_zh[tb + 1024 + o] = *(uint4*)&st[1024 + o];
        *(uint4*)&g_zl[tb + o]        = *(uint4*)&st[2048 + o];
        *(uint4*)&g_zl[tb + 1024 + o] = *(uint4*)&st[3072 + o];
        __syncthreads();
    }
    vpart += __shfl_xor_sync(0xffffffffu, vpart, 1);
    if (half == 0) g_v[row] = vpart;
}

// -------- presplit weights: WqT split (A), WkT hi (B), Wv hi (B) --------
__global__ __launch_bounds__(256) void presplit_weights(
    const float* __restrict__ Wq, const float* __restrict__ Wk,
    const float* __restrict__ Wv)
{
    const int which = blockIdx.y;
    const int idx = blockIdx.x * 256 + threadIdx.x;   // < 73728
    if (which == 0) {
        int d = idx / 192, fp = idx % 192;
        float x = Wq[(size_t)(2 * fp) * 384 + d];
        float y = Wq[(size_t)(2 * fp + 1) * 384 + d];
        uint32_t h, l; splitpack(x, y, h, l);
        size_t o = (size_t)((d >> 7) * 12 + (fp >> 4)) * TILE_U32 +
                   (offA(d & 127, fp & 15) >> 2);
        g_wqTh[o] = h; g_wqTl[o] = l;
    } else if (which == 1) {
        int e = idx / 192, fp = idx % 192;
        float x = Wk[(size_t)(2 * fp) * 384 + e];
        float y = Wk[(size_t)(2 * fp + 1) * 384 + e];
        size_t o = (size_t)((e >> 7) * 12 + (fp >> 4)) * TILE_U32 +
                   (offB(e & 127, fp & 15) >> 2);
        g_wkTh[o] = packh2(x, y);
    } else {
        int ng = idx / 192, kp = idx % 192;
        float2 vv = *(const float2*)&Wv[(size_t)ng * 384 + kp * 2];
        size_t o = (size_t)((ng >> 7) * 12 + (kp >> 4)) * TILE_U32 +
                   (offB(ng & 127, kp & 15) >> 2);
        g_wvh[o] = packh2(vv.x, vv.y);
    }
}

// ---------------------------------------------------------------------------
// 2-term fp16 GEMM: C = (Ah + Al) * Bh. A split, B plain fp16.
// MODE 0: Y & V projections grid(6,768)
// MODE 1: fused scores+exp -> P tiles + rowsums grid(6,256); B = z offA (hi)
// MODE 2: out = (P V) / rowsum grid(3,3,256)
// MODE 3: A = Wq^T Wk grid(3,3)
// ---------------------------------------------------------------------------
template <int MODE>
__global__ __launch_bounds__(NTH, 2) void gemm(
    const float* __restrict__ bias, float* __restrict__ outp)
{
    extern __shared__ __align__(16) char sm[];
    const uint32_t smb = smem_u32(sm);
    const int tid = threadIdx.x;
    const int lane = tid & 31;
    const int wid = tid >> 5;
    const int wm = wid >> 2;
    const int wn = wid & 3;

    const uint32_t *Ah, *Al, *Bh;
    int NKT, n0 = 0, m0 = 0, w = 0, mt = 0, b = 0;

    if (MODE == 0) {
        w = blockIdx.x / 3;                 // 0 = Y, 1 = V
        int nt = blockIdx.x % 3;
        n0 = nt * 128;
        Ah = g_zh + (size_t)blockIdx.y * 24576;
        Al = g_zl + (size_t)blockIdx.y * 24576;
        Bh = (w == 0) ? (g_Abh + nt * 12 * TILE_U32)
                      : (g_wvh + nt * 12 * TILE_U32);
        NKT = 12;
    } else if (MODE == 1) {
        const int mtab[6] = {0, 1, 1, 2, 2, 2};
        const int ntab[6] = {0, 0, 1, 0, 1, 2};
        mt = mtab[blockIdx.x];
        int nt = ntab[blockIdx.x];
        b = blockIdx.y;
        m0 = mt * 128; n0 = nt * 128;
        Ah = g_Yh + (size_t)(b * 3 + mt) * 24576;
        Al = g_Yl + (size_t)(b * 3 + mt) * 24576;
        Bh = g_zh + (size_t)(b * 3 + nt) * 24576;   // z offA tiles as B (hi)
        NKT = 12;
    } else if (MODE == 2) {
        int nt = blockIdx.x; mt = blockIdx.y; b = blockIdx.z;
        m0 = mt * 128; n0 = nt * 128;
        Ah = g_Ph + (size_t)(b * 3 + mt) * 24576;
        Al = g_Pl + (size_t)(b * 3 + mt) * 24576;
        Bh = g_Vth + (size_t)(b * 3 + nt) * 24576;
        NKT = (mt + 1) * 4;
    } else {
        int nt = blockIdx.x; mt = blockIdx.y;
        m0 = mt * 128; n0 = nt * 128;
        Ah = g_wqTh + (size_t)mt * 24576;
        Al = g_wqTl + (size_t)mt * 24576;
        Bh = g_wkTh + (size_t)nt * 24576;
        NKT = 12;
    }

    auto issue = [&](int kt, int st) {
        const uint32_t d0 = smb + st * STAGE_BYTES + tid * 16;
        const int go = kt * TILE_U32 + tid * 4;
        CP16(d0,         Ah + go);  CP16(d0 + 4096,  Ah + go + 1024);
        CP16(d0 + 8192,  Al + go);  CP16(d0 + 12288, Al + go + 1024);
        CP16(d0 + 16384, Bh + go);  CP16(d0 + 20480, Bh + go + 1024);
    };

    issue(0, 0); CP_COMMIT();
    issue(1, 1); CP_COMMIT();

    float acc[4][4][4];
#pragma unroll
    for (int i = 0; i < 4; i++)
#pragma unroll
        for (int j = 0; j < 4; j++)
#pragma unroll
            for (int r = 0; r < 4; r++) acc[i][j][r] = 0.0f;

    int cs = 0, is = 2;
    for (int kt = 0; kt < NKT; kt++) {
        CP_WAIT1();
        __syncthreads();
        if (kt + 2 < NKT) issue(kt + 2, is);
        CP_COMMIT();

        const char* base = sm + cs * STAGE_BYTES;
#pragma unroll
        for (int s = 0; s < 2; s++) {
            uint4 ah[4], al[4];
#pragma unroll
            for (int i = 0; i < 4; i++) {
                int off = s * 4096 + (wm * 4 + i) * 512 + lane * 16;
                ah[i] = *(const uint4*)(base + off);
                al[i] = *(const uint4*)(base + 8192 + off);
            }
            if (MODE == 1) {
                // B tiles are offA layout: one uint4 = two n8k16 B fragments
#pragma unroll
                for (int jj = 0; jj < 2; jj++) {
                    int off = s * 4096 + (wn * 2 + jj) * 512 + lane * 16;
                    uint4 bhv = *(const uint4*)(base + 16384 + off);
                    uint2 bh0 = make_uint2(bhv.x, bhv.z);
                    uint2 bh1 = make_uint2(bhv.y, bhv.w);
                    const int j0 = jj * 2, j1 = jj * 2 + 1;
#pragma unroll
                    for (int i = 0; i < 4; i++) MMA(acc[i][j0], ah[i], bh0);
#pragma unroll
                    for (int i = 0; i < 4; i++) MMA(acc[i][j1], ah[i], bh1);
#pragma unroll
                    for (int i = 0; i < 4; i++) MMA(acc[i][j0], al[i], bh0);
#pragma unroll
                    for (int i = 0; i < 4; i++) MMA(acc[i][j1], al[i], bh1);
                }
            } else {
#pragma unroll
                for (int j = 0; j < 4; j++) {
                    int off = s * 4096 + (wn * 4 + j) * 256 + lane * 8;
                    uint2 bh = *(const uint2*)(base + 16384 + off);
#pragma unroll
                    for (int i = 0; i < 4; i++) MMA(acc[i][j], ah[i], bh);
#pragma unroll
                    for (int i = 0; i < 4; i++) MMA(acc[i][j], al[i], bh);
                }
            }
        }
        cs = (cs == 2) ? 0 : cs + 1;
        is = (is == 2) ? 0 : is + 1;
    }

    // ---- epilogues ----
    const int g = lane >> 2, t = lane & 3;

    if (MODE == 0 && w == 0) {
        // Y: stage split fragment tile in smem, coalesced write
        CP_WAIT0();
        __syncthreads();
        uint32_t* sp = (uint32_t*)sm;   // hi 32KB, lo at +8192 u32
#pragma unroll
        for (int i = 0; i < 4; i++) {
            const int rl = wm * 64 + i * 16 + g;
#pragma unroll
            for (int j = 0; j < 4; j++) {
                const int c0 = n0 + wn * 32 + j * 8 + t * 2;
                uint32_t h0, l0, h1, l1;
                splitpack(acc[i][j][0], acc[i][j][1], h0, l0);
                splitpack(acc[i][j][2], acc[i][j][3], h1, l1);
                int kp = (c0 - n0) >> 1;
                int sub = kp >> 4, kpp = kp & 15;
                int o1 = (sub * 8192 + offA(rl, kpp)) >> 2;
                int o2 = (sub * 8192 + offA(rl + 8, kpp)) >> 2;
                sp[o1] = h0; sp[8192 + o1] = l0;
                sp[o2] = h1; sp[8192 + o2] = l1;
            }
        }
        __syncthreads();
        size_t gb = ((size_t)blockIdx.y * 12 + (n0 >> 5)) * TILE_U32;
#pragma unroll
        for (int s4 = 0; s4 < 4; s4++) {
#pragma unroll
            for (int it = 0; it < 2; it++) {
                int o = it * 1024 + tid * 4;
                *(uint4*)&g_Yh[gb + s4 * 2048 + o] = *(const uint4*)&sp[s4 * 2048 + o];
                *(uint4*)&g_Yl[gb + s4 * 2048 + o] = *(const uint4*)&sp[8192 + s4 * 2048 + o];
            }
        }
    } else if (MODE == 0) {
        // V: fp32 transpose staging, then hi-only fragment staging + coalesced
        CP_WAIT0();
        __syncthreads();
        float* s = (float*)sm;   // [128][132]
#pragma unroll
        for (int i = 0; i < 4; i++) {
            const int rl = wm * 64 + i * 16 + g;
#pragma unroll
            for (int j = 0; j < 4; j++) {
                const int c = wn * 32 + j * 8 + t * 2;
                float b0 = bias[n0 + c], b1 = bias[n0 + c + 1];
                s[rl * 132 + c]           = acc[i][j][0] + b0;
                s[rl * 132 + c + 1]       = acc[i][j][1] + b1;
                s[(rl + 8) * 132 + c]     = acc[i][j][2] + b0;
                s[(rl + 8) * 132 + c + 1] = acc[i][j][3] + b1;
            }
        }
        __syncthreads();
        uint32_t* fh = (uint32_t*)(sm + 69632);   // 8KB
        const int bb = blockIdx.y / 3;
        const int l0tok = (blockIdx.y % 3) * 128;
        const int dl = tid & 127;
        const int pb = (tid >> 7) * 8;
#pragma unroll
        for (int sub = 0; sub < 4; sub++) {
            int tb = sub * 32;
#pragma unroll
            for (int pp = 0; pp < 8; pp++) {
                int p = pb + pp;
                float x = s[(tb + 2 * p) * 132 + dl];
                float y = s[(tb + 2 * p + 1) * 132 + dl];
                fh[offB(dl, p) >> 2] = packh2(x, y);
            }
            __syncthreads();
            int tok0 = l0tok + tb;
            size_t tile = (size_t)((bb * 3 + (n0 >> 7)) * 12 + (tok0 >> 5)) * TILE_U32;
            int o = tid * 4;
            *(uint4*)&g_Vth[tile + o]        = *(const uint4*)&fh[o];
            *(uint4*)&g_Vth[tile + 1024 + o] = *(const uint4*)&fh[1024 + o];
            __syncthreads();
        }
    } else if (MODE == 1) {
        // fused: mask + exp (unnormalized) + rowsums + coalesced P tiles
        CP_WAIT0();
        __syncthreads();
        uint32_t* sp = (uint32_t*)sm;           // staging: hi 32KB, lo 32KB
        float* rs4 = (float*)(sm + 65536);      // [4][128]
        float* vsm = (float*)(sm + 67584);      // [128]
        if (tid < 128) vsm[tid] = g_v[(size_t)b * 384 + n0 + tid];
        __syncthreads();

        float rsum[4][2];
#pragma unroll
        for (int i = 0; i < 4; i++) { rsum[i][0] = 0.0f; rsum[i][1] = 0.0f; }

#pragma unroll
        for (int i = 0; i < 4; i++) {
            const int rl = wm * 64 + i * 16 + g;
            const int q0 = m0 + rl, q1 = q0 + 8;
#pragma unroll
            for (int j = 0; j < 4; j++) {
                const int c0 = n0 + wn * 32 + j * 8 + t * 2;
                const int cl = c0 - n0;
                float vk0 = vsm[cl], vk1 = vsm[cl + 1];
                float p0 = (c0     <= q0) ? fast_exp((acc[i][j][0] + vk0) * INV_SQRT_D) : 0.0f;
                float p1 = (c0 + 1 <= q0) ? fast_exp((acc[i][j][1] + vk1) * INV_SQRT_D) : 0.0f;
                float p2 = (c0     <= q1) ? fast_exp((acc[i][j][2] + vk0) * INV_SQRT_D) : 0.0f;
                float p3 = (c0 + 1 <= q1) ? fast_exp((acc[i][j][3] + vk1) * INV_SQRT_D) : 0.0f;
                rsum[i][0] += p0 + p1;
                rsum[i][1] += p2 + p3;
                uint32_t h0, l0, h1, l1;
                splitpack(p0, p1, h0, l0);
                splitpack(p2, p3, h1, l1);
                int kp = cl >> 1;
                int sub = kp >> 4, kpp = kp & 15;
                int o1 = (sub * 8192 + offA(rl, kpp)) >> 2;
                int o2 = (sub * 8192 + offA(rl + 8, kpp)) >> 2;
                sp[o1] = h0; sp[8192 + o1] = l0;
                sp[o2] = h1; sp[8192 + o2] = l1;
            }
        }
#pragma unroll
        for (int i = 0; i < 4; i++) {
#pragma unroll
            for (int h = 0; h < 2; h++) {
                rsum[i][h] += __shfl_xor_sync(0xffffffffu, rsum[i][h], 1);
                rsum[i][h] += __shfl_xor_sync(0xffffffffu, rsum[i][h], 2);
            }
        }
        if (t == 0) {
#pragma unroll
            for (int i = 0; i < 4; i++) {
                int rl = wm * 64 + i * 16 + g;
                rs4[wn * 128 + rl]     = rsum[i][0];
                rs4[wn * 128 + rl + 8] = rsum[i][1];
            }
        }
        __syncthreads();
        size_t gbase = ((size_t)(b * 3 + mt) * 12 + (n0 >> 5)) * TILE_U32;
#pragma unroll
        for (int s4 = 0; s4 < 4; s4++) {
            size_t tb = gbase + s4 * TILE_U32;
#pragma unroll
            for (int it = 0; it < 2; it++) {
                int o = it * 1024 + tid * 4;
                *(uint4*)&g_Ph[tb + o] = *(const uint4*)&sp[s4 * 2048 + o];
                *(uint4*)&g_Pl[tb + o] = *(const uint4*)&sp[8192 + s4 * 2048 + o];
            }
        }
        if (tid < 128) {
            float ssum = rs4[tid] + rs4[128 + tid] + rs4[256 + tid] + rs4[384 + tid];
            g_rsp[(size_t)(n0 >> 7) * 98304 + (size_t)b * 384 + m0 + tid] = ssum;
        }
    } else if (MODE == 2) {
        float* Oo = outp + (size_t)b * BSTRIDE;
#pragma unroll
        for (int i = 0; i < 4; i++) {
            const int r0 = m0 + wm * 64 + i * 16 + g;
            float s0 = 0.0f, s1 = 0.0f;
            for (int k = 0; k <= mt; k++) {
                s0 += g_rsp[(size_t)k * 98304 + (size_t)b * 384 + r0];
                s1 += g_rsp[(size_t)k * 98304 + (size_t)b * 384 + r0 + 8];
            }
            float inv0 = 1.0f / s0, inv1 = 1.0f / s1;
#pragma unroll
            for (int j = 0; j < 4; j++) {
                const int c0 = n0 + wn * 32 + j * 8 + t * 2;
                *(float2*)&Oo[(size_t)r0 * 384 + c0] =
                    make_float2(acc[i][j][0] * inv0, acc[i][j][1] * inv0);
                *(float2*)&Oo[(size_t)(r0 + 8) * 384 + c0] =
                    make_float2(acc[i][j][2] * inv1, acc[i][j][3] * inv1);
            }
        }
    } else {
        // MODE 3: A[d,e] -> transpose-write g_Abh as offB (hi only; tiny)
        CP_WAIT0();
        __syncthreads();
        float* s = (float*)sm;   // [128 d][132 e]
#pragma unroll
        for (int i = 0; i < 4; i++) {
            const int rl = wm * 64 + i * 16 + g;
#pragma unroll
            for (int j = 0; j < 4; j++) {
                const int c = wn * 32 + j * 8 + t * 2;
                s[rl * 132 + c]           = acc[i][j][0];
                s[rl * 132 + c + 1]       = acc[i][j][1];
                s[(rl + 8) * 132 + c]     = acc[i][j][2];
                s[(rl + 8) * 132 + c + 1] = acc[i][j][3];
            }
        }
        __syncthreads();
#pragma unroll
        for (int it = 0; it < 8; it++) {
            int idx = it * 256 + tid;
            int el = idx & 127;
            int db = (idx >> 7) * 8;
            float v[8];
#pragma unroll
            for (int u = 0; u < 8; u++) v[u] = s[(db + u) * 132 + el];
            int k0 = m0 + db;
            size_t tile = (size_t)((n0 >> 7) * 12 + (k0 >> 5)) * TILE_U32;
            int p0 = (k0 & 31) >> 1;
#pragma unroll
            for (int pp = 0; pp < 4; pp++) {
                size_t o = tile + (offB(el, p0 + pp) >> 2);
                g_Abh[o] = packh2(v[2 * pp], v[2 * pp + 1]);
            }
        }
    }
}

// ---------------------------------------------------------------------------
extern "C" void kernel_launch(void* const* d_in, const int* in_sizes, int n_in,
                              void* d_out, int out_size)
{
    const float* z  = (const float*)d_in[0];
    const float* Wq = (const float*)d_in[1];
    const float* bq = (const float*)d_in[2];
    const float* Wk = (const float*)d_in[3];
    const float* Wv = (const float*)d_in[5];
    const float* bv = (const float*)d_in[6];
    float* out = (float*)d_out;

    cudaFuncSetAttribute(gemm<0>, cudaFuncAttributeMaxDynamicSharedMemorySize, SMEM_BYTES);
    cudaFuncSetAttribute(gemm<1>, cudaFuncAttributeMaxDynamicSharedMemorySize, SMEM_BYTES);
    cudaFuncSetAttribute(gemm<2>, cudaFuncAttributeMaxDynamicSharedMemorySize, SMEM_BYTES);
    cudaFuncSetAttribute(gemm<3>, cudaFuncAttributeMaxDynamicSharedMemorySize, SMEM_BYTES);

    dim3 blk(NTH);

    a2_kernel<<<1, 384>>>(Wk, bq);
    presplit_z<<<768, blk>>>(z);
    presplit_weights<<<dim3(288, 3), blk>>>(Wq, Wk, Wv);

    // A = Wq^T Wk (tiny)
    gemm<3><<<dim3(3, 3), blk, SMEM_BYTES>>>(nullptr, nullptr);

    // Y = z A (offA split) and V = z Wv^T + bv (offB hi, transposed)
    gemm<0><<<dim3(6, 768), blk, SMEM_BYTES>>>(bv, nullptr);

    // fused scores + exp -> P tiles + rowsum partials (lower triangle only)
    gemm<1><<<dim3(6, 256), blk, SMEM_BYTES>>>(nullptr, nullptr);

    // out = (P V) / rowsum
    gemm<2><<<dim3(3, 3, 256), blk, SMEM_BYTES>>>(nullptr, out);
}

// round 12
// speedup vs baseline: 2.2068x; 1.1847x over previous
#include <cuda_runtime.h>
#include <cuda_fp16.h>
#include <stdint.h>

#define NTH 256
#define BSTRIDE 147456               // floats per batch (384*384)
static const float INV_SQRT_D = 0.05103103630798288f;

#define NPAIR 18874368               // 256*384*192
#define TILE_U32 2048                // uint32 per 128x32 fragment tile (8KB)
#define WTILES (36 * TILE_U32)

// fragment-ordered 128x32 operand tiles (fp16 pairs)
__device__ uint32_t g_zh[NPAIR],  g_zl[NPAIR];    // z, offA (A-op split; B via uint4 trick hi)
__device__ uint32_t g_Yh[NPAIR];                  // Y = z*(Wq^T Wk), offA (A-op, hi only)
__device__ uint32_t g_Vth[NPAIR];                 // V transposed, offB (B-op, hi only)
__device__ uint32_t g_Ph[NPAIR];                  // exp(scores), offA (A-op, hi only)
__device__ uint32_t g_wqTh[WTILES], g_wqTl[WTILES];  // Wq^T, offA (A-op split)
__device__ uint32_t g_wkTh[WTILES];                  // Wk^T, offB
__device__ uint32_t g_wvh[WTILES];                   // Wv rows, offB
__device__ uint32_t g_Abh[WTILES];                   // A=Wq^T Wk, offB
__device__ float    g_a2[384];                       // Wk^T bq
__device__ float    g_v[98304];                      // z . a2
__device__ float    g_rsp[3 * 98304];                // per-kt row partial sums

__device__ __forceinline__ int offA(int r, int p) {
    return ((p >> 3) << 12) + ((r >> 4) << 9) +
           (((r & 7) * 4 + (p & 3)) << 4) +
           (((p >> 2) & 1) << 3) + (((r >> 3) & 1) << 2);
}
__device__ __forceinline__ int offB(int n, int p) {
    return ((p >> 3) << 12) + ((n >> 3) << 8) +
           (((n & 7) * 4 + (p & 3)) << 3) + (((p >> 2) & 1) << 2);
}

#define MMA(d, a, b) \
    asm volatile("mma.sync.aligned.m16n8k16.row.col.f32.f16.f16.f32 " \
        "{%0,%1,%2,%3},{%4,%5,%6,%7},{%8,%9},{%0,%1,%2,%3};" \
        : "+f"((d)[0]), "+f"((d)[1]), "+f"((d)[2]), "+f"((d)[3]) \
        : "r"((a).x), "r"((a).y), "r"((a).z), "r"((a).w), \
          "r"((b).x), "r"((b).y))

#define CP16(sa, gp) \
    asm volatile("cp.async.cg.shared.global [%0], [%1], 16;" :: "r"(sa), "l"(gp))
#define CP_COMMIT() asm volatile("cp.async.commit_group;" ::: "memory")
#define CP_WAIT1()  asm volatile("cp.async.wait_group 1;" ::: "memory")
#define CP_WAIT0()  asm volatile("cp.async.wait_group 0;" ::: "memory")

__device__ __forceinline__ uint32_t smem_u32(const void* p) {
    uint32_t a;
    asm("{ .reg .u64 t; cvta.to.shared.u64 t, %1; cvt.u32.u64 %0, t; }"
        : "=r"(a) : "l"(p));
    return a;
}

// fp16 split: hi = fp16(x), lo = fp16(x - hi)
__device__ __forceinline__ void splitpack(float x, float y,
                                          uint32_t& hi, uint32_t& lo) {
    __half hx = __float2half_rn(x);
    __half hy = __float2half_rn(y);
    float lx = x - __half2float(hx);
    float ly = y - __half2float(hy);
    __half2 h2 = __halves2half2(hx, hy);
    __half2 l2 = __floats2half2_rn(lx, ly);
    hi = reinterpret_cast<uint32_t&>(h2);
    lo = reinterpret_cast<uint32_t&>(l2);
}
__device__ __forceinline__ uint32_t packh2(float x, float y) {
    __half2 h2 = __floats2half2_rn(x, y);
    return reinterpret_cast<uint32_t&>(h2);
}

// fast e^x on the FMA pipe (poly exp2, rel err ~2e-6)
__device__ __forceinline__ float fast_exp(float x) {
    float y = x * 1.4426950408889634f;
    int ir = __float2int_rn(y);
    float f = (y - (float)ir) * 0.6931471805599453f;
    float p = 1.0f + f * (1.0f + f * (0.5f + f * (0.16666667f +
              f * (0.041666667f + f * 0.0083333333f))));
    return p * __int_as_float((ir + 127) << 23);
}

// ---------------- a2 = Wk^T bq ----------------
__global__ void a2_kernel(const float* __restrict__ Wk,
                          const float* __restrict__ bq) {
    int d = threadIdx.x;
    float s = 0.0f;
    for (int f = 0; f < 384; f++) s += Wk[(size_t)f * 384 + d] * bq[f];
    g_a2[d] = s;
}

// -------- presplit z (tiled, coalesced): offA tiles + v = z.a2 --------
__global__ __launch_bounds__(256) void presplit_z(const float* __restrict__ z) {
    __shared__ __align__(16) uint32_t st[4096];   // 16KB staging (hi | lo)
    const int tid = threadIdx.x;
    const int rt = blockIdx.x;                    // 0..767 row tile
    const int rl = tid >> 1;                      // local row 0..127
    const int half = tid & 1;
    const int row = (rt << 7) + rl;
    float vpart = 0.0f;

    for (int kt = 0; kt < 12; kt++) {
        const float* zp = z + (size_t)row * 384 + kt * 32 + half * 16;
        float vbuf[16];
        *(float4*)&vbuf[0]  = *(const float4*)(zp);
        *(float4*)&vbuf[4]  = *(const float4*)(zp + 4);
        *(float4*)&vbuf[8]  = *(const float4*)(zp + 8);
        *(float4*)&vbuf[12] = *(const float4*)(zp + 12);

        const float* ap = g_a2 + kt * 32 + half * 16;
        float abuf[16];
        *(float4*)&abuf[0]  = *(const float4*)(ap);
        *(float4*)&abuf[4]  = *(const float4*)(ap + 4);
        *(float4*)&abuf[8]  = *(const float4*)(ap + 8);
        *(float4*)&abuf[12] = *(const float4*)(ap + 12);
#pragma unroll
        for (int c = 0; c < 16; c++) vpart += vbuf[c] * abuf[c];

#pragma unroll
        for (int p = 0; p < 8; p++) {
            uint32_t h, l;
            splitpack(vbuf[2 * p], vbuf[2 * p + 1], h, l);
            int pp = half * 8 + p;
            int oA = offA(rl, pp) >> 2;
            st[oA] = h; st[2048 + oA] = l;
        }
        __syncthreads();

        size_t tb = (size_t)(rt * 12 + kt) * TILE_U32;
        int o = tid * 4;
        *(uint4*)&g_zh[tb + o]        = *(uint4*)&st[o];
        *(uint4*)&g_zh[tb + 1024 + o] = *(uint4*)&st[1024 + o];
        *(uint4*)&g_zl[tb + o]        = *(uint4*)&st[2048 + o];
        *(uint4*)&g_zl[tb + 1024 + o] = *(uint4*)&st[3072 + o];
        __syncthreads();
    }
    vpart += __shfl_xor_sync(0xffffffffu, vpart, 1);
    if (half == 0) g_v[row] = vpart;
}

// -------- presplit weights: WqT split (A), WkT hi (B), Wv hi (B) --------
__global__ __launch_bounds__(256) void presplit_weights(
    const float* __restrict__ Wq, const float* __restrict__ Wk,
    const float* __restrict__ Wv)
{
    const int which = blockIdx.y;
    const int idx = blockIdx.x * 256 + threadIdx.x;   // < 73728
    if (which == 0) {
        int d = idx / 192, fp = idx % 192;
        float x = Wq[(size_t)(2 * fp) * 384 + d];
        float y = Wq[(size_t)(2 * fp + 1) * 384 + d];
        uint32_t h, l; splitpack(x, y, h, l);
        size_t o = (size_t)((d >> 7) * 12 + (fp >> 4)) * TILE_U32 +
                   (offA(d & 127, fp & 15) >> 2);
        g_wqTh[o] = h; g_wqTl[o] = l;
    } else if (which == 1) {
        int e = idx / 192, fp = idx % 192;
        float x = Wk[(size_t)(2 * fp) * 384 + e];
        float y = Wk[(size_t)(2 * fp + 1) * 384 + e];
        size_t o = (size_t)((e >> 7) * 12 + (fp >> 4)) * TILE_U32 +
                   (offB(e & 127, fp & 15) >> 2);
        g_wkTh[o] = packh2(x, y);
    } else {
        int ng = idx / 192, kp = idx % 192;
        float2 vv = *(const float2*)&Wv[(size_t)ng * 384 + kp * 2];
        size_t o = (size_t)((ng >> 7) * 12 + (kp >> 4)) * TILE_U32 +
                   (offB(ng & 127, kp & 15) >> 2);
        g_wvh[o] = packh2(vv.x, vv.y);
    }
}

// ---------------------------------------------------------------------------
// MODE 0: Y & V projections grid(6,768)        A = z (2-term), B hi
// MODE 1: fused scores+exp grid(6,256)         A = Y (1-term), B = z hi (offA trick)
// MODE 2: out = (P V)/rowsum grid(3,3,256)     A = P (1-term), B = Vt hi
// MODE 3: A = Wq^T Wk grid(3,3)                A = WqT (2-term), B = WkT hi
// ---------------------------------------------------------------------------
template <int MODE>
__global__ __launch_bounds__(NTH, 2) void gemm(
    const float* __restrict__ bias, float* __restrict__ outp)
{
    constexpr bool ALO = (MODE == 0 || MODE == 3);      // A has lo term
    constexpr int SB = ALO ? 24576 : 16384;             // stage bytes
    constexpr int BO = ALO ? 16384 : 8192;              // B offset in stage

    extern __shared__ __align__(16) char sm[];
    const uint32_t smb = smem_u32(sm);
    const int tid = threadIdx.x;
    const int lane = tid & 31;
    const int wid = tid >> 5;
    const int wm = wid >> 2;
    const int wn = wid & 3;

    const uint32_t *Ah, *Al = nullptr, *Bh;
    int NKT, n0 = 0, m0 = 0, w = 0, mt = 0, b = 0;

    if (MODE == 0) {
        w = blockIdx.x / 3;                 // 0 = Y, 1 = V
        int nt = blockIdx.x % 3;
        n0 = nt * 128;
        Ah = g_zh + (size_t)blockIdx.y * 24576;
        Al = g_zl + (size_t)blockIdx.y * 24576;
        Bh = (w == 0) ? (g_Abh + nt * 12 * TILE_U32)
                      : (g_wvh + nt * 12 * TILE_U32);
        NKT = 12;
    } else if (MODE == 1) {
        const int mtab[6] = {0, 1, 1, 2, 2, 2};
        const int ntab[6] = {0, 0, 1, 0, 1, 2};
        mt = mtab[blockIdx.x];
        int nt = ntab[blockIdx.x];
        b = blockIdx.y;
        m0 = mt * 128; n0 = nt * 128;
        Ah = g_Yh + (size_t)(b * 3 + mt) * 24576;
        Bh = g_zh + (size_t)(b * 3 + nt) * 24576;   // z offA tiles as B (hi)
        NKT = 12;
    } else if (MODE == 2) {
        int nt = blockIdx.x; mt = blockIdx.y; b = blockIdx.z;
        m0 = mt * 128; n0 = nt * 128;
        Ah = g_Ph + (size_t)(b * 3 + mt) * 24576;
        Bh = g_Vth + (size_t)(b * 3 + nt) * 24576;
        NKT = (mt + 1) * 4;
    } else {
        int nt = blockIdx.x; mt = blockIdx.y;
        m0 = mt * 128; n0 = nt * 128;
        Ah = g_wqTh + (size_t)mt * 24576;
        Al = g_wqTl + (size_t)mt * 24576;
        Bh = g_wkTh + (size_t)nt * 24576;
        NKT = 12;
    }

    auto issue = [&](int kt, int st) {
        const uint32_t d0 = smb + st * SB + tid * 16;
        const int go = kt * TILE_U32 + tid * 4;
        CP16(d0,        Ah + go);  CP16(d0 + 4096,      Ah + go + 1024);
        if (ALO) { CP16(d0 + 8192, Al + go); CP16(d0 + 12288, Al + go + 1024); }
        CP16(d0 + BO,   Bh + go);  CP16(d0 + BO + 4096, Bh + go + 1024);
    };

    issue(0, 0); CP_COMMIT();
    issue(1, 1); CP_COMMIT();

    float acc[4][4][4];
#pragma unroll
    for (int i = 0; i < 4; i++)
#pragma unroll
        for (int j = 0; j < 4; j++)
#pragma unroll
            for (int r = 0; r < 4; r++) acc[i][j][r] = 0.0f;

    int cs = 0, is = 2;
    for (int kt = 0; kt < NKT; kt++) {
        CP_WAIT1();
        __syncthreads();
        if (kt + 2 < NKT) issue(kt + 2, is);
        CP_COMMIT();

        const char* base = sm + cs * SB;
#pragma unroll
        for (int s = 0; s < 2; s++) {
            uint4 ah[4], al[4];
#pragma unroll
            for (int i = 0; i < 4; i++) {
                int off = s * 4096 + (wm * 4 + i) * 512 + lane * 16;
                ah[i] = *(const uint4*)(base + off);
                if (ALO) al[i] = *(const uint4*)(base + 8192 + off);
            }
            if (MODE == 1) {
                // B tiles are offA layout: one uint4 = two n8k16 B fragments
#pragma unroll
                for (int jj = 0; jj < 2; jj++) {
                    int off = s * 4096 + (wn * 2 + jj) * 512 + lane * 16;
                    uint4 bhv = *(const uint4*)(base + BO + off);
                    uint2 bh0 = make_uint2(bhv.x, bhv.z);
                    uint2 bh1 = make_uint2(bhv.y, bhv.w);
                    const int j0 = jj * 2, j1 = jj * 2 + 1;
#pragma unroll
                    for (int i = 0; i < 4; i++) MMA(acc[i][j0], ah[i], bh0);
#pragma unroll
                    for (int i = 0; i < 4; i++) MMA(acc[i][j1], ah[i], bh1);
                }
            } else {
#pragma unroll
                for (int j = 0; j < 4; j++) {
                    int off = s * 4096 + (wn * 4 + j) * 256 + lane * 8;
                    uint2 bh = *(const uint2*)(base + BO + off);
#pragma unroll
                    for (int i = 0; i < 4; i++) MMA(acc[i][j], ah[i], bh);
                    if (ALO) {
#pragma unroll
                        for (int i = 0; i < 4; i++) MMA(acc[i][j], al[i], bh);
                    }
                }
            }
        }
        cs = (cs == 2) ? 0 : cs + 1;
        is = (is == 2) ? 0 : is + 1;
    }

    // ---- epilogues ----
    const int g = lane >> 2, t = lane & 3;

    if (MODE == 0 && w == 0) {
        // Y: stage hi fragment tile in smem, coalesced write
        CP_WAIT0();
        __syncthreads();
        uint32_t* sp = (uint32_t*)sm;   // hi 32KB
#pragma unroll
        for (int i = 0; i < 4; i++) {
            const int rl = wm * 64 + i * 16 + g;
#pragma unroll
            for (int j = 0; j < 4; j++) {
                const int c0 = n0 + wn * 32 + j * 8 + t * 2;
                uint32_t h0 = packh2(acc[i][j][0], acc[i][j][1]);
                uint32_t h1 = packh2(acc[i][j][2], acc[i][j][3]);
                int kp = (c0 - n0) >> 1;
                int sub = kp >> 4, kpp = kp & 15;
                sp[(sub * 8192 + offA(rl, kpp)) >> 2] = h0;
                sp[(sub * 8192 + offA(rl + 8, kpp)) >> 2] = h1;
            }
        }
        __syncthreads();
        size_t gb = ((size_t)blockIdx.y * 12 + (n0 >> 5)) * TILE_U32;
#pragma unroll
        for (int s4 = 0; s4 < 4; s4++) {
#pragma unroll
            for (int it = 0; it < 2; it++) {
                int o = it * 1024 + tid * 4;
                *(uint4*)&g_Yh[gb + s4 * 2048 + o] = *(const uint4*)&sp[s4 * 2048 + o];
            }
        }
    } else if (MODE == 0) {
        // V: fp32 transpose staging, then hi-only fragment staging + coalesced
        CP_WAIT0();
        __syncthreads();
        float* s = (float*)sm;   // [128][132]
#pragma unroll
        for (int i = 0; i < 4; i++) {
            const int rl = wm * 64 + i * 16 + g;
#pragma unroll
            for (int j = 0; j < 4; j++) {
                const int c = wn * 32 + j * 8 + t * 2;
                float b0 = bias[n0 + c], b1 = bias[n0 + c + 1];
                s[rl * 132 + c]           = acc[i][j][0] + b0;
                s[rl * 132 + c + 1]       = acc[i][j][1] + b1;
                s[(rl + 8) * 132 + c]     = acc[i][j][2] + b0;
                s[(rl + 8) * 132 + c + 1] = acc[i][j][3] + b1;
            }
        }
        __syncthreads();
        uint32_t* fh = (uint32_t*)(sm + 69632);   // 8KB
        const int bb = blockIdx.y / 3;
        const int l0tok = (blockIdx.y % 3) * 128;
        const int dl = tid & 127;
        const int pb = (tid >> 7) * 8;
#pragma unroll
        for (int sub = 0; sub < 4; sub++) {
            int tb = sub * 32;
#pragma unroll
            for (int pp = 0; pp < 8; pp++) {
                int p = pb + pp;
                float x = s[(tb + 2 * p) * 132 + dl];
                float y = s[(tb + 2 * p + 1) * 132 + dl];
                fh[offB(dl, p) >> 2] = packh2(x, y);
            }
            __syncthreads();
            int tok0 = l0tok + tb;
            size_t tile = (size_t)((bb * 3 + (n0 >> 7)) * 12 + (tok0 >> 5)) * TILE_U32;
            int o = tid * 4;
            *(uint4*)&g_Vth[tile + o]        = *(const uint4*)&fh[o];
            *(uint4*)&g_Vth[tile + 1024 + o] = *(const uint4*)&fh[1024 + o];
            __syncthreads();
        }
    } else if (MODE == 1) {
        // fused: mask + exp (unnormalized) + rowsums + coalesced hi P tiles
        CP_WAIT0();
        __syncthreads();
        uint32_t* sp = (uint32_t*)sm;           // staging: hi 32KB
        float* rs4 = (float*)(sm + 32768);      // [4][128]
        float* vsm = (float*)(sm + 34816);      // [128]
        if (tid < 128) vsm[tid] = g_v[(size_t)b * 384 + n0 + tid];
        __syncthreads();

        float rsum[4][2];
#pragma unroll
        for (int i = 0; i < 4; i++) { rsum[i][0] = 0.0f; rsum[i][1] = 0.0f; }

#pragma unroll
        for (int i = 0; i < 4; i++) {
            const int rl = wm * 64 + i * 16 + g;
            const int q0 = m0 + rl, q1 = q0 + 8;
#pragma unroll
            for (int j = 0; j < 4; j++) {
                const int c0 = n0 + wn * 32 + j * 8 + t * 2;
                const int cl = c0 - n0;
                float vk0 = vsm[cl], vk1 = vsm[cl + 1];
                float p0 = (c0     <= q0) ? fast_exp((acc[i][j][0] + vk0) * INV_SQRT_D) : 0.0f;
                float p1 = (c0 + 1 <= q0) ? fast_exp((acc[i][j][1] + vk1) * INV_SQRT_D) : 0.0f;
                float p2 = (c0     <= q1) ? fast_exp((acc[i][j][2] + vk0) * INV_SQRT_D) : 0.0f;
                float p3 = (c0 + 1 <= q1) ? fast_exp((acc[i][j][3] + vk1) * INV_SQRT_D) : 0.0f;
                rsum[i][0] += p0 + p1;
                rsum[i][1] += p2 + p3;
                int kp = cl >> 1;
                int sub = kp >> 4, kpp = kp & 15;
                sp[(sub * 8192 + offA(rl, kpp)) >> 2]     = packh2(p0, p1);
                sp[(sub * 8192 + offA(rl + 8, kpp)) >> 2] = packh2(p2, p3);
            }
        }
#pragma unroll
        for (int i = 0; i < 4; i++) {
#pragma unroll
            for (int h = 0; h < 2; h++) {
                rsum[i][h] += __shfl_xor_sync(0xffffffffu, rsum[i][h], 1);
                rsum[i][h] += __shfl_xor_sync(0xffffffffu, rsum[i][h], 2);
            }
        }
        if (t == 0) {
#pragma unroll
            for (int i = 0; i < 4; i++) {
                int rl = wm * 64 + i * 16 + g;
                rs4[wn * 128 + rl]     = rsum[i][0];
                rs4[wn * 128 + rl + 8] = rsum[i][1];
            }
        }
        __syncthreads();
        size_t gbase = ((size_t)(b * 3 + mt) * 12 + (n0 >> 5)) * TILE_U32;
#pragma unroll
        for (int s4 = 0; s4 < 4; s4++) {
            size_t tb = gbase + s4 * TILE_U32;
#pragma unroll
            for (int it = 0; it < 2; it++) {
                int o = it * 1024 + tid * 4;
                *(uint4*)&g_Ph[tb + o] = *(const uint4*)&sp[s4 * 2048 + o];
            }
        }
        if (tid < 128) {
            float ssum = rs4[tid] + rs4[128 + tid] + rs4[256 + tid] + rs4[384 + tid];
            g_rsp[(size_t)(n0 >> 7) * 98304 + (size_t)b * 384 + m0 + tid] = ssum;
        }
    } else if (MODE == 2) {
        float* Oo = outp + (size_t)b * BSTRIDE;
#pragma unroll
        for (int i = 0; i < 4; i++) {
            const int r0 = m0 + wm * 64 + i * 16 + g;
            float s0 = 0.0f, s1 = 0.0f;
            for (int k = 0; k <= mt; k++) {
                s0 += g_rsp[(size_t)k * 98304 + (size_t)b * 384 + r0];
                s1 += g_rsp[(size_t)k * 98304 + (size_t)b * 384 + r0 + 8];
            }
            float inv0 = 1.0f / s0, inv1 = 1.0f / s1;
#pragma unroll
            for (int j = 0; j < 4; j++) {
                const int c0 = n0 + wn * 32 + j * 8 + t * 2;
                *(float2*)&Oo[(size_t)r0 * 384 + c0] =
                    make_float2(acc[i][j][0] * inv0, acc[i][j][1] * inv0);
                *(float2*)&Oo[(size_t)(r0 + 8) * 384 + c0] =
                    make_float2(acc[i][j][2] * inv1, acc[i][j][3] * inv1);
            }
        }
    } else {
        // MODE 3: A[d,e] -> transpose-write g_Abh as offB (hi only; tiny)
        CP_WAIT0();
        __syncthreads();
        float* s = (float*)sm;   // [128 d][132 e]
#pragma unroll
        for (int i = 0; i < 4; i++) {
            const int rl = wm * 64 + i * 16 + g;
#pragma unroll
            for (int j = 0; j < 4; j++) {
                const int c = wn * 32 + j * 8 + t * 2;
                s[rl * 132 + c]           = acc[i][j][0];
                s[rl * 132 + c + 1]       = acc[i][j][1];
                s[(rl + 8) * 132 + c]     = acc[i][j][2];
                s[(rl + 8) * 132 + c + 1] = acc[i][j][3];
            }
        }
        __syncthreads();
#pragma unroll
        for (int it = 0; it < 8; it++) {
            int idx = it * 256 + tid;
            int el = idx & 127;
            int db = (idx >> 7) * 8;
            float v[8];
#pragma unroll
            for (int u = 0; u < 8; u++) v[u] = s[(db + u) * 132 + el];
            int k0 = m0 + db;
            size_t tile = (size_t)((n0 >> 7) * 12 + (k0 >> 5)) * TILE_U32;
            int p0 = (k0 & 31) >> 1;
#pragma unroll
            for (int pp = 0; pp < 4; pp++) {
                size_t o = tile + (offB(el, p0 + pp) >> 2);
                g_Abh[o] = packh2(v[2 * pp], v[2 * pp + 1]);
            }
        }
    }
}

// ---------------------------------------------------------------------------
extern "C" void kernel_launch(void* const* d_in, const int* in_sizes, int n_in,
                              void* d_out, int out_size)
{
    const float* z  = (const float*)d_in[0];
    const float* Wq = (const float*)d_in[1];
    const float* bq = (const float*)d_in[2];
    const float* Wk = (const float*)d_in[3];
    const float* Wv = (const float*)d_in[5];
    const float* bv = (const float*)d_in[6];
    float* out = (float*)d_out;

    const int SM0 = 77824;   // 3*24576 loop; V epi needs 69632+8192
    const int SM1 = 49152;   // 3*16384 loop; epi needs ~35KB
    const int SM2 = 49152;
    const int SM3 = 73728;   // 3*24576 loop; epi needs 67.6KB

    cudaFuncSetAttribute(gemm<0>, cudaFuncAttributeMaxDynamicSharedMemorySize, SM0);
    cudaFuncSetAttribute(gemm<1>, cudaFuncAttributeMaxDynamicSharedMemorySize, SM1);
    cudaFuncSetAttribute(gemm<2>, cudaFuncAttributeMaxDynamicSharedMemorySize, SM2);
    cudaFuncSetAttribute(gemm<3>, cudaFuncAttributeMaxDynamicSharedMemorySize, SM3);

    dim3 blk(NTH);

    a2_kernel<<<1, 384>>>(Wk, bq);
    presplit_z<<<768, blk>>>(z);
    presplit_weights<<<dim3(288, 3), blk>>>(Wq, Wk, Wv);

    // A = Wq^T Wk (tiny)
    gemm<3><<<dim3(3, 3), blk, SM3>>>(nullptr, nullptr);

    // Y = z A (offA hi) and V = z Wv^T + bv (offB hi, transposed)
    gemm<0><<<dim3(6, 768), blk, SM0>>>(bv, nullptr);

    // fused scores + exp -> P hi tiles + rowsum partials (lower triangle only)
    gemm<1><<<dim3(6, 256), blk, SM1>>>(nullptr, nullptr);

    // out = (P V) / rowsum
    gemm<2><<<dim3(3, 3, 256), blk, SM2>>>(nullptr, out);
}

// round 13
// speedup vs baseline: 2.9207x; 1.3235x over previous
#include <cuda_runtime.h>
#include <cuda_fp16.h>
#include <stdint.h>

#define NTH 256
#define BSTRIDE 147456               // floats per batch (384*384)
static const float INV_SQRT_D = 0.05103103630798288f;

#define NPAIR 18874368               // 256*384*192
#define TILE_U32 2048                // uint32 per 128x32 fragment tile (8KB)
#define WTILES (36 * TILE_U32)

// fragment-ordered 128x32 operand tiles (fp16 pairs, hi precision level noted)
__device__ uint32_t g_zh[NPAIR];                  // z, offA (A-op hi; B via uint4 trick)
__device__ uint32_t g_Yh[NPAIR];                  // Y = z*(Wq^T Wk), offA hi
__device__ uint32_t g_Vth[NPAIR];                 // V transposed, offB hi
__device__ uint32_t g_Ph[NPAIR];                  // exp(scores), offA hi
__device__ uint32_t g_wqTh[WTILES], g_wqTl[WTILES];  // Wq^T, offA split (tiny gemm)
__device__ uint32_t g_wkTh[WTILES];                  // Wk^T, offB
__device__ uint32_t g_wvh[WTILES];                   // Wv rows, offB
__device__ uint32_t g_Abh[WTILES];                   // A=Wq^T Wk, offB
__device__ float    g_a2[384];                       // Wk^T bq
__device__ float    g_v[98304];                      // z . a2
__device__ float    g_rsp[3 * 98304];                // per-kt row partial sums

__device__ __forceinline__ int offA(int r, int p) {
    return ((p >> 3) << 12) + ((r >> 4) << 9) +
           (((r & 7) * 4 + (p & 3)) << 4) +
           (((p >> 2) & 1) << 3) + (((r >> 3) & 1) << 2);
}
__device__ __forceinline__ int offB(int n, int p) {
    return ((p >> 3) << 12) + ((n >> 3) << 8) +
           (((n & 7) * 4 + (p & 3)) << 3) + (((p >> 2) & 1) << 2);
}

#define MMA(d, a, b) \
    asm volatile("mma.sync.aligned.m16n8k16.row.col.f32.f16.f16.f32 " \
        "{%0,%1,%2,%3},{%4,%5,%6,%7},{%8,%9},{%0,%1,%2,%3};" \
        : "+f"((d)[0]), "+f"((d)[1]), "+f"((d)[2]), "+f"((d)[3]) \
        : "r"((a).x), "r"((a).y), "r"((a).z), "r"((a).w), \
          "r"((b).x), "r"((b).y))

#define CP16(sa, gp) \
    asm volatile("cp.async.cg.shared.global [%0], [%1], 16;" :: "r"(sa), "l"(gp))
#define CP_COMMIT() asm volatile("cp.async.commit_group;" ::: "memory")
#define CP_WAIT1()  asm volatile("cp.async.wait_group 1;" ::: "memory")
#define CP_WAIT0()  asm volatile("cp.async.wait_group 0;" ::: "memory")

__device__ __forceinline__ uint32_t smem_u32(const void* p) {
    uint32_t a;
    asm("{ .reg .u64 t; cvta.to.shared.u64 t, %1; cvt.u32.u64 %0, t; }"
        : "=r"(a) : "l"(p));
    return a;
}

// fp16 split: hi = fp16(x), lo = fp16(x - hi)
__device__ __forceinline__ void splitpack(float x, float y,
                                          uint32_t& hi, uint32_t& lo) {
    __half hx = __float2half_rn(x);
    __half hy = __float2half_rn(y);
    float lx = x - __half2float(hx);
    float ly = y - __half2float(hy);
    __half2 h2 = __halves2half2(hx, hy);
    __half2 l2 = __floats2half2_rn(lx, ly);
    hi = reinterpret_cast<uint32_t&>(h2);
    lo = reinterpret_cast<uint32_t&>(l2);
}
__device__ __forceinline__ uint32_t packh2(float x, float y) {
    __half2 h2 = __floats2half2_rn(x, y);
    return reinterpret_cast<uint32_t&>(h2);
}

// fast e^x on the FMA pipe (poly exp2, rel err ~2e-6)
__device__ __forceinline__ float fast_exp(float x) {
    float y = x * 1.4426950408889634f;
    int ir = __float2int_rn(y);
    float f = (y - (float)ir) * 0.6931471805599453f;
    float p = 1.0f + f * (1.0f + f * (0.5f + f * (0.16666667f +
              f * (0.041666667f + f * 0.0083333333f))));
    return p * __int_as_float((ir + 127) << 23);
}

// ---------------- a2 = Wk^T bq ----------------
__global__ void a2_kernel(const float* __restrict__ Wk,
                          const float* __restrict__ bq) {
    int d = threadIdx.x;
    float s = 0.0f;
    for (int f = 0; f < 384; f++) s += Wk[(size_t)f * 384 + d] * bq[f];
    g_a2[d] = s;
}

// -------- presplit z (tiled, coalesced): offA hi tiles + v = z.a2 --------
__global__ __launch_bounds__(256) void presplit_z(const float* __restrict__ z) {
    __shared__ __align__(16) uint32_t st[2048];   // 8KB staging (hi)
    const int tid = threadIdx.x;
    const int rt = blockIdx.x;                    // 0..767 row tile
    const int rl = tid >> 1;                      // local row 0..127
    const int half = tid & 1;
    const int row = (rt << 7) + rl;
    float vpart = 0.0f;

    for (int kt = 0; kt < 12; kt++) {
        const float* zp = z + (size_t)row * 384 + kt * 32 + half * 16;
        float vbuf[16];
        *(float4*)&vbuf[0]  = *(const float4*)(zp);
        *(float4*)&vbuf[4]  = *(const float4*)(zp + 4);
        *(float4*)&vbuf[8]  = *(const float4*)(zp + 8);
        *(float4*)&vbuf[12] = *(const float4*)(zp + 12);

        const float* ap = g_a2 + kt * 32 + half * 16;
        float abuf[16];
        *(float4*)&abuf[0]  = *(const float4*)(ap);
        *(float4*)&abuf[4]  = *(const float4*)(ap + 4);
        *(float4*)&abuf[8]  = *(const float4*)(ap + 8);
        *(float4*)&abuf[12] = *(const float4*)(ap + 12);
#pragma unroll
        for (int c = 0; c < 16; c++) vpart += vbuf[c] * abuf[c];

#pragma unroll
        for (int p = 0; p < 8; p++) {
            int pp = half * 8 + p;
            st[offA(rl, pp) >> 2] = packh2(vbuf[2 * p], vbuf[2 * p + 1]);
        }
        __syncthreads();

        size_t tb = (size_t)(rt * 12 + kt) * TILE_U32;
        int o = tid * 4;
        *(uint4*)&g_zh[tb + o]        = *(uint4*)&st[o];
        *(uint4*)&g_zh[tb + 1024 + o] = *(uint4*)&st[1024 + o];
        __syncthreads();
    }
    vpart += __shfl_xor_sync(0xffffffffu, vpart, 1);
    if (half == 0) g_v[row] = vpart;
}

// -------- presplit weights: WqT split (A), WkT hi (B), Wv hi (B) --------
__global__ __launch_bounds__(256) void presplit_weights(
    const float* __restrict__ Wq, const float* __restrict__ Wk,
    const float* __restrict__ Wv)
{
    const int which = blockIdx.y;
    const int idx = blockIdx.x * 256 + threadIdx.x;   // < 73728
    if (which == 0) {
        int d = idx / 192, fp = idx % 192;
        float x = Wq[(size_t)(2 * fp) * 384 + d];
        float y = Wq[(size_t)(2 * fp + 1) * 384 + d];
        uint32_t h, l; splitpack(x, y, h, l);
        size_t o = (size_t)((d >> 7) * 12 + (fp >> 4)) * TILE_U32 +
                   (offA(d & 127, fp & 15) >> 2);
        g_wqTh[o] = h; g_wqTl[o] = l;
    } else if (which == 1) {
        int e = idx / 192, fp = idx % 192;
        float x = Wk[(size_t)(2 * fp) * 384 + e];
        float y = Wk[(size_t)(2 * fp + 1) * 384 + e];
        size_t o = (size_t)((e >> 7) * 12 + (fp >> 4)) * TILE_U32 +
                   (offB(e & 127, fp & 15) >> 2);
        g_wkTh[o] = packh2(x, y);
    } else {
        int ng = idx / 192, kp = idx % 192;
        float2 vv = *(const float2*)&Wv[(size_t)ng * 384 + kp * 2];
        size_t o = (size_t)((ng >> 7) * 12 + (kp >> 4)) * TILE_U32 +
                   (offB(ng & 127, kp & 15) >> 2);
        g_wvh[o] = packh2(vv.x, vv.y);
    }
}

// ---------------------------------------------------------------------------
// MODE 0: Y & V projections grid(6,768)        A = z hi, B hi
// MODE 1: fused scores+exp grid(6,256)         A = Y hi, B = z hi (offA trick)
// MODE 2: out = (P V)/rowsum grid(3,3,256)     A = P hi, B = Vt hi
// MODE 3: A = Wq^T Wk grid(3,3)                A = WqT split (2-term), B = WkT
// ---------------------------------------------------------------------------
template <int MODE>
__global__ __launch_bounds__(NTH, 2) void gemm(
    const float* __restrict__ bias, float* __restrict__ outp)
{
    constexpr bool ALO = (MODE == 3);                   // A has lo term
    constexpr int SB = ALO ? 24576 : 16384;             // stage bytes
    constexpr int BO = ALO ? 16384 : 8192;              // B offset in stage

    extern __shared__ __align__(16) char sm[];
    const uint32_t smb = smem_u32(sm);
    const int tid = threadIdx.x;
    const int lane = tid & 31;
    const int wid = tid >> 5;
    const int wm = wid >> 2;
    const int wn = wid & 3;

    const uint32_t *Ah, *Al = nullptr, *Bh;
    int NKT, n0 = 0, m0 = 0, w = 0, mt = 0, b = 0;

    if (MODE == 0) {
        w = blockIdx.x / 3;                 // 0 = Y, 1 = V
        int nt = blockIdx.x % 3;
        n0 = nt * 128;
        Ah = g_zh + (size_t)blockIdx.y * 24576;
        Bh = (w == 0) ? (g_Abh + nt * 12 * TILE_U32)
                      : (g_wvh + nt * 12 * TILE_U32);
        NKT = 12;
    } else if (MODE == 1) {
        const int mtab[6] = {0, 1, 1, 2, 2, 2};
        const int ntab[6] = {0, 0, 1, 0, 1, 2};
        mt = mtab[blockIdx.x];
        int nt = ntab[blockIdx.x];
        b = blockIdx.y;
        m0 = mt * 128; n0 = nt * 128;
        Ah = g_Yh + (size_t)(b * 3 + mt) * 24576;
        Bh = g_zh + (size_t)(b * 3 + nt) * 24576;   // z offA tiles as B
        NKT = 12;
    } else if (MODE == 2) {
        int nt = blockIdx.x; mt = blockIdx.y; b = blockIdx.z;
        m0 = mt * 128; n0 = nt * 128;
        Ah = g_Ph + (size_t)(b * 3 + mt) * 24576;
        Bh = g_Vth + (size_t)(b * 3 + nt) * 24576;
        NKT = (mt + 1) * 4;
    } else {
        int nt = blockIdx.x; mt = blockIdx.y;
        m0 = mt * 128; n0 = nt * 128;
        Ah = g_wqTh + (size_t)mt * 24576;
        Al = g_wqTl + (size_t)mt * 24576;
        Bh = g_wkTh + (size_t)nt * 24576;
        NKT = 12;
    }

    auto issue = [&](int kt, int st) {
        const uint32_t d0 = smb + st * SB + tid * 16;
        const int go = kt * TILE_U32 + tid * 4;
        CP16(d0,        Ah + go);  CP16(d0 + 4096,      Ah + go + 1024);
        if (ALO) { CP16(d0 + 8192, Al + go); CP16(d0 + 12288, Al + go + 1024); }
        CP16(d0 + BO,   Bh + go);  CP16(d0 + BO + 4096, Bh + go + 1024);
    };

    issue(0, 0); CP_COMMIT();
    issue(1, 1); CP_COMMIT();

    float acc[4][4][4];
#pragma unroll
    for (int i = 0; i < 4; i++)
#pragma unroll
        for (int j = 0; j < 4; j++)
#pragma unroll
            for (int r = 0; r < 4; r++) acc[i][j][r] = 0.0f;

    int cs = 0, is = 2;
    for (int kt = 0; kt < NKT; kt++) {
        CP_WAIT1();
        __syncthreads();
        if (kt + 2 < NKT) issue(kt + 2, is);
        CP_COMMIT();

        const char* base = sm + cs * SB;
#pragma unroll
        for (int s = 0; s < 2; s++) {
            uint4 ah[4], al[4];
#pragma unroll
            for (int i = 0; i < 4; i++) {
                int off = s * 4096 + (wm * 4 + i) * 512 + lane * 16;
                ah[i] = *(const uint4*)(base + off);
                if (ALO) al[i] = *(const uint4*)(base + 8192 + off);
            }
            if (MODE == 1) {
                // B tiles are offA layout: one uint4 = two n8k16 B fragments
#pragma unroll
                for (int jj = 0; jj < 2; jj++) {
                    int off = s * 4096 + (wn * 2 + jj) * 512 + lane * 16;
                    uint4 bhv = *(const uint4*)(base + BO + off);
                    uint2 bh0 = make_uint2(bhv.x, bhv.z);
                    uint2 bh1 = make_uint2(bhv.y, bhv.w);
                    const int j0 = jj * 2, j1 = jj * 2 + 1;
#pragma unroll
                    for (int i = 0; i < 4; i++) MMA(acc[i][j0], ah[i], bh0);
#pragma unroll
                    for (int i = 0; i < 4; i++) MMA(acc[i][j1], ah[i], bh1);
                }
            } else {
#pragma unroll
                for (int j = 0; j < 4; j++) {
                    int off = s * 4096 + (wn * 4 + j) * 256 + lane * 8;
                    uint2 bh = *(const uint2*)(base + BO + off);
#pragma unroll
                    for (int i = 0; i < 4; i++) MMA(acc[i][j], ah[i], bh);
                    if (ALO) {
#pragma unroll
                        for (int i = 0; i < 4; i++) MMA(acc[i][j], al[i], bh);
                    }
                }
            }
        }
        cs = (cs == 2) ? 0 : cs + 1;
        is = (is == 2) ? 0 : is + 1;
    }

    // ---- epilogues ----
    const int g = lane >> 2, t = lane & 3;

    if (MODE == 0 && w == 0) {
        // Y: stage hi fragment tile in smem, coalesced write
        CP_WAIT0();
        __syncthreads();
        uint32_t* sp = (uint32_t*)sm;   // hi 32KB
#pragma unroll
        for (int i = 0; i < 4; i++) {
            const int rl = wm * 64 + i * 16 + g;
#pragma unroll
            for (int j = 0; j < 4; j++) {
                const int c0 = n0 + wn * 32 + j * 8 + t * 2;
                uint32_t h0 = packh2(acc[i][j][0], acc[i][j][1]);
                uint32_t h1 = packh2(acc[i][j][2], acc[i][j][3]);
                int kp = (c0 - n0) >> 1;
                int sub = kp >> 4, kpp = kp & 15;
                sp[(sub * 8192 + offA(rl, kpp)) >> 2] = h0;
                sp[(sub * 8192 + offA(rl + 8, kpp)) >> 2] = h1;
            }
        }
        __syncthreads();
        size_t gb = ((size_t)blockIdx.y * 12 + (n0 >> 5)) * TILE_U32;
#pragma unroll
        for (int s4 = 0; s4 < 4; s4++) {
#pragma unroll
            for (int it = 0; it < 2; it++) {
                int o = it * 1024 + tid * 4;
                *(uint4*)&g_Yh[gb + s4 * 2048 + o] = *(const uint4*)&sp[s4 * 2048 + o];
            }
        }
    } else if (MODE == 0) {
        // V: fp32 transpose staging, then hi fragment staging + coalesced
        CP_WAIT0();
        __syncthreads();
        float* s = (float*)sm;   // [128][132]
#pragma unroll
        for (int i = 0; i < 4; i++) {
            const int rl = wm * 64 + i * 16 + g;
#pragma unroll
            for (int j = 0; j < 4; j++) {
                const int c = wn * 32 + j * 8 + t * 2;
                float b0 = bias[n0 + c], b1 = bias[n0 + c + 1];
                s[rl * 132 + c]           = acc[i][j][0] + b0;
                s[rl * 132 + c + 1]       = acc[i][j][1] + b1;
                s[(rl + 8) * 132 + c]     = acc[i][j][2] + b0;
                s[(rl + 8) * 132 + c + 1] = acc[i][j][3] + b1;
            }
        }
        __syncthreads();
        uint32_t* fh = (uint32_t*)(sm + 69632);   // 8KB
        const int bb = blockIdx.y / 3;
        const int l0tok = (blockIdx.y % 3) * 128;
        const int dl = tid & 127;
        const int pb = (tid >> 7) * 8;
#pragma unroll
        for (int sub = 0; sub < 4; sub++) {
            int tb = sub * 32;
#pragma unroll
            for (int pp = 0; pp < 8; pp++) {
                int p = pb + pp;
                float x = s[(tb + 2 * p) * 132 + dl];
                float y = s[(tb + 2 * p + 1) * 132 + dl];
                fh[offB(dl, p) >> 2] = packh2(x, y);
            }
            __syncthreads();
            int tok0 = l0tok + tb;
            size_t tile = (size_t)((bb * 3 + (n0 >> 7)) * 12 + (tok0 >> 5)) * TILE_U32;
            int o = tid * 4;
            *(uint4*)&g_Vth[tile + o]        = *(const uint4*)&fh[o];
            *(uint4*)&g_Vth[tile + 1024 + o] = *(const uint4*)&fh[1024 + o];
            __syncthreads();
        }
    } else if (MODE == 1) {
        // fused: mask + exp (unnormalized) + rowsums + coalesced hi P tiles
        CP_WAIT0();
        __syncthreads();
        uint32_t* sp = (uint32_t*)sm;           // staging: hi 32KB
        float* rs4 = (float*)(sm + 32768);      // [4][128]
        float* vsm = (float*)(sm + 34816);      // [128]
        if (tid < 128) vsm[tid] = g_v[(size_t)b * 384 + n0 + tid];
        __syncthreads();

        float rsum[4][2];
#pragma unroll
        for (int i = 0; i < 4; i++) { rsum[i][0] = 0.0f; rsum[i][1] = 0.0f; }

#pragma unroll
        for (int i = 0; i < 4; i++) {
            const int rl = wm * 64 + i * 16 + g;
            const int q0 = m0 + rl, q1 = q0 + 8;
#pragma unroll
            for (int j = 0; j < 4; j++) {
                const int c0 = n0 + wn * 32 + j * 8 + t * 2;
                const int cl = c0 - n0;
                float vk0 = vsm[cl], vk1 = vsm[cl + 1];
                float p0 = (c0     <= q0) ? fast_exp((acc[i][j][0] + vk0) * INV_SQRT_D) : 0.0f;
                float p1 = (c0 + 1 <= q0) ? fast_exp((acc[i][j][1] + vk1) * INV_SQRT_D) : 0.0f;
                float p2 = (c0     <= q1) ? fast_exp((acc[i][j][2] + vk0) * INV_SQRT_D) : 0.0f;
                float p3 = (c0 + 1 <= q1) ? fast_exp((acc[i][j][3] + vk1) * INV_SQRT_D) : 0.0f;
                rsum[i][0] += p0 + p1;
                rsum[i][1] += p2 + p3;
                int kp = cl >> 1;
                int sub = kp >> 4, kpp = kp & 15;
                sp[(sub * 8192 + offA(rl, kpp)) >> 2]     = packh2(p0, p1);
                sp[(sub * 8192 + offA(rl + 8, kpp)) >> 2] = packh2(p2, p3);
            }
        }
#pragma unroll
        for (int i = 0; i < 4; i++) {
#pragma unroll
            for (int h = 0; h < 2; h++) {
                rsum[i][h] += __shfl_xor_sync(0xffffffffu, rsum[i][h], 1);
                rsum[i][h] += __shfl_xor_sync(0xffffffffu, rsum[i][h], 2);
            }
        }
        if (t == 0) {
#pragma unroll
            for (int i = 0; i < 4; i++) {
                int rl = wm * 64 + i * 16 + g;
                rs4[wn * 128 + rl]     = rsum[i][0];
                rs4[wn * 128 + rl + 8] = rsum[i][1];
            }
        }
        __syncthreads();
        size_t gbase = ((size_t)(b * 3 + mt) * 12 + (n0 >> 5)) * TILE_U32;
#pragma unroll
        for (int s4 = 0; s4 < 4; s4++) {
            size_t tb = gbase + s4 * TILE_U32;
#pragma unroll
            for (int it = 0; it < 2; it++) {
                int o = it * 1024 + tid * 4;
                *(uint4*)&g_Ph[tb + o] = *(const uint4*)&sp[s4 * 2048 + o];
            }
        }
        if (tid < 128) {
            float ssum = rs4[tid] + rs4[128 + tid] + rs4[256 + tid] + rs4[384 + tid];
            g_rsp[(size_t)(n0 >> 7) * 98304 + (size_t)b * 384 + m0 + tid] = ssum;
        }
    } else if (MODE == 2) {
        float* Oo = outp + (size_t)b * BSTRIDE;
#pragma unroll
        for (int i = 0; i < 4; i++) {
            const int r0 = m0 + wm * 64 + i * 16 + g;
            float s0 = 0.0f, s1 = 0.0f;
            for (int k = 0; k <= mt; k++) {
                s0 += g_rsp[(size_t)k * 98304 + (size_t)b * 384 + r0];
                s1 += g_rsp[(size_t)k * 98304 + (size_t)b * 384 + r0 + 8];
            }
            float inv0 = 1.0f / s0, inv1 = 1.0f / s1;
#pragma unroll
            for (int j = 0; j < 4; j++) {
                const int c0 = n0 + wn * 32 + j * 8 + t * 2;
                *(float2*)&Oo[(size_t)r0 * 384 + c0] =
                    make_float2(acc[i][j][0] * inv0, acc[i][j][1] * inv0);
                *(float2*)&Oo[(size_t)(r0 + 8) * 384 + c0] =
                    make_float2(acc[i][j][2] * inv1, acc[i][j][3] * inv1);
            }
        }
    } else {
        // MODE 3: A[d,e] -> transpose-write g_Abh as offB (hi only; tiny)
        CP_WAIT0();
        __syncthreads();
        float* s = (float*)sm;   // [128 d][132 e]
#pragma unroll
        for (int i = 0; i < 4; i++) {
            const int rl = wm * 64 + i * 16 + g;
#pragma unroll
            for (int j = 0; j < 4; j++) {
                const int c = wn * 32 + j * 8 + t * 2;
                s[rl * 132 + c]           = acc[i][j][0];
                s[rl * 132 + c + 1]       = acc[i][j][1];
                s[(rl + 8) * 132 + c]     = acc[i][j][2];
                s[(rl + 8) * 132 + c + 1] = acc[i][j][3];
            }
        }
        __syncthreads();
#pragma unroll
        for (int it = 0; it < 8; it++) {
            int idx = it * 256 + tid;
            int el = idx & 127;
            int db = (idx >> 7) * 8;
            float v[8];
#pragma unroll
            for (int u = 0; u < 8; u++) v[u] = s[(db + u) * 132 + el];
            int k0 = m0 + db;
            size_t tile = (size_t)((n0 >> 7) * 12 + (k0 >> 5)) * TILE_U32;
            int p0 = (k0 & 31) >> 1;
#pragma unroll
            for (int pp = 0; pp < 4; pp++) {
                size_t o = tile + (offB(el, p0 + pp) >> 2);
                g_Abh[o] = packh2(v[2 * pp], v[2 * pp + 1]);
            }
        }
    }
}

// ---------------------------------------------------------------------------
extern "C" void kernel_launch(void* const* d_in, const int* in_sizes, int n_in,
                              void* d_out, int out_size)
{
    const float* z  = (const float*)d_in[0];
    const float* Wq = (const float*)d_in[1];
    const float* bq = (const float*)d_in[2];
    const float* Wk = (const float*)d_in[3];
    const float* Wv = (const float*)d_in[5];
    const float* bv = (const float*)d_in[6];
    float* out = (float*)d_out;

    const int SM0 = 77824;   // 3*16384 loop; V epi needs 69632+8192
    const int SM1 = 49152;   // 3*16384 loop; epi ~35KB
    const int SM2 = 49152;
    const int SM3 = 73728;   // 3*24576 loop; epi 67.6KB

    cudaFuncSetAttribute(gemm<0>, cudaFuncAttributeMaxDynamicSharedMemorySize, SM0);
    cudaFuncSetAttribute(gemm<1>, cudaFuncAttributeMaxDynamicSharedMemorySize, SM1);
    cudaFuncSetAttribute(gemm<2>, cudaFuncAttributeMaxDynamicSharedMemorySize, SM2);
    cudaFuncSetAttribute(gemm<3>, cudaFuncAttributeMaxDynamicSharedMemorySize, SM3);

    dim3 blk(NTH);

    a2_kernel<<<1, 384>>>(Wk, bq);
    presplit_z<<<768, blk>>>(z);
    presplit_weights<<<dim3(288, 3), blk>>>(Wq, Wk, Wv);

    // A = Wq^T Wk (tiny, 2-term for accuracy)
    gemm<3><<<dim3(3, 3), blk, SM3>>>(nullptr, nullptr);

    // Y = z A (offA hi) and V = z Wv^T + bv (offB hi, transposed)
    gemm<0><<<dim3(6, 768), blk, SM0>>>(bv, nullptr);

    // fused scores + exp -> P hi tiles + rowsum partials (lower triangle only)
    gemm<1><<<dim3(6, 256), blk, SM1>>>(nullptr, nullptr);

    // out = (P V) / rowsum
    gemm<2><<<dim3(3, 3, 256), blk, SM2>>>(nullptr, out);
}